// round 3
// baseline (speedup 1.0000x reference)
#include <cuda_runtime.h>
#include <cstdint>

#define BB 16
#define HH 96
#define WW 128
#define HWW (HH*WW)          // 12288
#define NPIX (BB*HWW)        // 196608
#define CP 196

// ---------------- packed-f32x2 helpers -----------------------------------------
__device__ __forceinline__ unsigned long long pack2(float x, float y) {
    unsigned long long r;
    asm("mov.b64 %0, {%1, %2};" : "=l"(r) : "f"(x), "f"(y));
    return r;
}
__device__ __forceinline__ void ffma2(unsigned long long& acc,
                                      unsigned long long a, unsigned long long b) {
    asm("fma.rn.f32x2 %0, %1, %2, %0;" : "+l"(acc) : "l"(a), "l"(b));
}
__device__ __forceinline__ float2 unpack2(unsigned long long v) {
    float2 f;
    asm("mov.b64 {%0, %1}, %2;" : "=f"(f.x), "=f"(f.y) : "l"(v));
    return f;
}
__device__ __forceinline__ void cp16(uint32_t dst, const void* src) {
    asm volatile("cp.async.cg.shared.global [%0], [%1], 16;" :: "r"(dst), "l"(src));
}

// ---------------- device scratch ------------------------------------------------
__device__ __align__(16) float g_Wc1q[CP*96];     // [k][96]
__device__ __align__(16) float g_Wf1q[64*2];
__device__ __align__(16) float g_Wf2q[64*32];     // [k][32]
__device__ __align__(16) float g_Wdq[128*9];      // [c][9]
__device__ __align__(16) float g_Wpq[128*80];     // [c][80]
__device__ float g_corflo[(size_t)BB*128*HWW];

// ---------------- 1) per-tensor int8 symmetric fake quant ------------------------
__global__ void quant_kernel(const float* __restrict__ Wc1,
                             const float* __restrict__ Wf1,
                             const float* __restrict__ Wf2,
                             const float* __restrict__ Wd,
                             const float* __restrict__ Wp) {
    __shared__ float red[256];
    __shared__ float s_scale;
    int t = blockIdx.x;
    const float* src; int n;
    if      (t == 0) { src = Wc1; n = 96*CP;  }
    else if (t == 1) { src = Wf1; n = 64*2;   }
    else if (t == 2) { src = Wf2; n = 32*64;  }
    else if (t == 3) { src = Wd;  n = 128*9;  }
    else             { src = Wp;  n = 80*128; }

    float m = 0.f;
    for (int i = threadIdx.x; i < n; i += 256) m = fmaxf(m, fabsf(src[i]));
    red[threadIdx.x] = m;
    __syncthreads();
    for (int s = 128; s > 0; s >>= 1) {
        if (threadIdx.x < s) red[threadIdx.x] = fmaxf(red[threadIdx.x], red[threadIdx.x+s]);
        __syncthreads();
    }
    if (threadIdx.x == 0) s_scale = fmaxf(red[0], 1e-8f) / 127.f;
    __syncthreads();
    float sc = s_scale;

    for (int i = threadIdx.x; i < n; i += 256) {
        float q = rintf(src[i] / sc);
        q = fminf(fmaxf(q, -127.f), 127.f) * sc;
        if      (t == 0) { int o = i / CP,  k = i % CP; g_Wc1q[k*96 + o] = q; }
        else if (t == 1) g_Wf1q[i] = q;
        else if (t == 2) { int o = i / 64,  k = i % 64; g_Wf2q[k*32 + o] = q; }
        else if (t == 3) g_Wdq[i]  = q;
        else             { int o = i / 128, c = i % 128; g_Wpq[c*80 + o] = q; }
    }
}

// ---------------- 2) corr 1x1 196->96 : register-tiled GEMM ----------------------
// Block: 256 threads, 256 pixels, all 96 outputs. Thread: 4 pixels x 24 channels.
#define KC 28
#define NCHK 7
__global__ __launch_bounds__(256) void cor_kernel(const float* __restrict__ corr,
                                                  const float* __restrict__ bc1) {
    extern __shared__ __align__(16) float sm[];
    float* Ws = sm;                    // [196][96]
    float* bs = Ws + CP*96;            // 96
    float* Xs = bs + 96;               // [2][28][256]

    const int tid = threadIdx.x;
    {
        const float4* wsrc = (const float4*)g_Wc1q;
        float4* wdst = (float4*)Ws;
        #pragma unroll 1
        for (int i = tid; i < CP*96/4; i += 256) wdst[i] = wsrc[i];
        if (tid < 96) bs[tid] = bc1[tid];
    }

    const int pix0 = blockIdx.x * 256;
    const int b = pix0 / HWW, hw0 = pix0 % HWW;
    const float* cbase = corr + (size_t)b * CP * HWW + hw0;

    uint32_t xs_s = (uint32_t)__cvta_generic_to_shared(Xs);

    auto issue = [&](int c, int buf) {
        int e = tid;
        #pragma unroll
        for (int j = 0; j < 7; j++) {          // 7*256 = 1792 float4 = 28x256 floats
            int kk = e >> 6, off = e & 63;
            cp16(xs_s + (uint32_t)(((buf*KC + kk)*256 + off*4)*4),
                 cbase + (size_t)(c*KC + kk) * HWW + off*4);
            e += 256;
        }
        asm volatile("cp.async.commit_group;");
    };

    issue(0, 0);
    __syncthreads();   // Ws/bs visible

    const int po = tid >> 6, pg = tid & 63;    // 4 output-groups x 64 pixel-groups

    unsigned long long acc[48];                // [p=4][q=12] channel pairs
    #pragma unroll
    for (int q = 0; q < 12; q++) {
        unsigned long long bv = pack2(bs[24*po + 2*q], bs[24*po + 2*q + 1]);
        acc[q] = bv; acc[12+q] = bv; acc[24+q] = bv; acc[36+q] = bv;
    }

    for (int c = 0; c < NCHK; c++) {
        if (c + 1 < NCHK) {
            issue(c + 1, (c + 1) & 1);
            asm volatile("cp.async.wait_group 1;");
        } else {
            asm volatile("cp.async.wait_group 0;");
        }
        __syncthreads();
        const float4* xsb = (const float4*)(Xs + (c & 1) * KC * 256);
        const float*  wrb = Ws + c * KC * 96 + 24 * po;
        #pragma unroll 4
        for (int kk = 0; kk < KC; kk++) {
            float4 xv = xsb[kk*64 + pg];
            unsigned long long x0 = pack2(xv.x, xv.x);
            unsigned long long x1 = pack2(xv.y, xv.y);
            unsigned long long x2 = pack2(xv.z, xv.z);
            unsigned long long x3 = pack2(xv.w, xv.w);
            const ulonglong2* wr = (const ulonglong2*)(wrb + kk*96);
            #pragma unroll
            for (int q2 = 0; q2 < 6; q2++) {
                ulonglong2 w = wr[q2];
                ffma2(acc[     2*q2], x0, w.x); ffma2(acc[     2*q2+1], x0, w.y);
                ffma2(acc[12 + 2*q2], x1, w.x); ffma2(acc[12 + 2*q2+1], x1, w.y);
                ffma2(acc[24 + 2*q2], x2, w.x); ffma2(acc[24 + 2*q2+1], x2, w.y);
                ffma2(acc[36 + 2*q2], x3, w.x); ffma2(acc[36 + 2*q2+1], x3, w.y);
            }
        }
        __syncthreads();   // buffer reuse fence
    }

    float* ob = g_corflo + ((size_t)b*128 + 24*po) * HWW + hw0 + 4*pg;
    #pragma unroll
    for (int j = 0; j < 12; j++) {
        float2 f0 = unpack2(acc[j]),    f1 = unpack2(acc[12+j]);
        float2 f2 = unpack2(acc[24+j]), f3 = unpack2(acc[36+j]);
        float4 e = make_float4(fmaxf(f0.x,0.f), fmaxf(f1.x,0.f), fmaxf(f2.x,0.f), fmaxf(f3.x,0.f));
        float4 o = make_float4(fmaxf(f0.y,0.f), fmaxf(f1.y,0.f), fmaxf(f2.y,0.f), fmaxf(f3.y,0.f));
        *(float4*)(ob + (size_t)(2*j)   * HWW) = e;
        *(float4*)(ob + (size_t)(2*j+1) * HWW) = o;
    }
}

// ---------------- 3) flow 1x1 chain 2->64->32 + relu (channels 96..127) ----------
__global__ __launch_bounds__(256) void flo_kernel(const float* __restrict__ flow,
                                                  const float* __restrict__ bf1,
                                                  const float* __restrict__ bf2) {
    __shared__ __align__(16) float w1[128];
    __shared__ __align__(16) float w2[64*32];
    __shared__ float b1[64], b2[32];
    for (int i = threadIdx.x; i < 128;  i += 256) w1[i] = g_Wf1q[i];
    for (int i = threadIdx.x; i < 64;   i += 256) b1[i] = bf1[i];
    for (int i = threadIdx.x; i < 2048; i += 256) w2[i] = g_Wf2q[i];
    for (int i = threadIdx.x; i < 32;   i += 256) b2[i] = bf2[i];
    __syncthreads();

    int p  = blockIdx.x * 256 + threadIdx.x;
    int b  = p / HWW, hw = p % HWW;
    float fx = flow[(size_t)b * 2 * HWW + hw];
    float fy = flow[(size_t)b * 2 * HWW + HWW + hw];

    unsigned long long acc[16];
    #pragma unroll
    for (int q = 0; q < 16; q++) acc[q] = pack2(b2[2*q], b2[2*q+1]);

    #pragma unroll 4
    for (int j = 0; j < 64; j++) {
        float h = fmaxf(fmaf(fx, w1[2*j], fmaf(fy, w1[2*j+1], b1[j])), 0.f);
        unsigned long long hh = pack2(h, h);
        const ulonglong2* wv = reinterpret_cast<const ulonglong2*>(w2 + j*32);
        #pragma unroll
        for (int q = 0; q < 8; q++) {
            ulonglong2 a = wv[q];
            ffma2(acc[2*q],   hh, a.x);
            ffma2(acc[2*q+1], hh, a.y);
        }
    }

    float* obase = g_corflo + ((size_t)b * 128 + 96) * HWW + hw;
    #pragma unroll
    for (int q = 0; q < 16; q++) {
        float2 f = unpack2(acc[q]);
        obase[(size_t)(2*q)   * HWW] = fmaxf(f.x, 0.f);
        obase[(size_t)(2*q+1) * HWW] = fmaxf(f.y, 0.f);
    }
}

// ---------------- 4) fused dw3x3 + pw 128->80 : two-phase, register-tiled --------
// Block: 256 threads, tile 64w x 4h = 256 pixels. Chunks of 16 channels.
// Phase A: depthwise into smem dwbuf. Phase B: GEMM, thread = 4 pix x 20 outputs.
#define DWB_STRIDE 272
__global__ __launch_bounds__(256) void dwpw_kernel(const float* __restrict__ flow,
                                                   const float* __restrict__ bp,
                                                   float* __restrict__ out) {
    extern __shared__ __align__(16) float sm2[];
    float* wp  = sm2;               // 128*80 = 10240
    float* wd  = wp + 10240;        // 128*9  = 1152
    float* bps = wd + 1152;         // 80
    float* it  = bps + 80;          // 16 * 6*68 = 6528
    float* dwb = it + 6528;         // 16 * 272  = 4352

    const int tid = threadIdx.x;
    for (int i = tid; i < 10240/4; i += 256) ((float4*)wp)[i] = ((const float4*)g_Wpq)[i];
    for (int i = tid; i < 1152;    i += 256) wd[i] = g_Wdq[i];
    if (tid < 80) bps[tid] = bp[tid];

    const int blk = blockIdx.x;                 // 768 blocks
    const int b = blk / 48, t = blk % 48;
    const int gy0 = (t >> 1) * 4, gx0 = (t & 1) * 64;

    const int po = tid >> 6, pg = tid & 63;     // GEMM tiling
    const int cl = tid >> 4, px16 = tid & 15;   // dw tiling

    __syncthreads();

    unsigned long long acc[40];                 // [p=4][q=10] channel pairs
    #pragma unroll
    for (int q = 0; q < 10; q++) {
        unsigned long long bv = pack2(bps[20*po + 2*q], bps[20*po + 2*q + 1]);
        acc[q] = bv; acc[10+q] = bv; acc[20+q] = bv; acc[30+q] = bv;
    }

    const float* cfb = g_corflo + (size_t)b * 128 * HWW;

    for (int c0 = 0; c0 < 128; c0 += 16) {
        __syncthreads();
        // load input halo tile: 16 ch x 6 rows x 66 cols
        #pragma unroll 1
        for (int i = tid; i < 16*6*66; i += 256) {
            int c = i / 396, r = i % 396;
            int ry = r / 66, rx = r % 66;
            int gy = gy0 - 1 + ry, gx = gx0 - 1 + rx;
            float v = 0.f;
            if (gy >= 0 && gy < HH && gx >= 0 && gx < WW)
                v = cfb[(size_t)(c0 + c) * HWW + gy * WW + gx];
            it[c*408 + ry*68 + rx] = v;
        }
        __syncthreads();
        // phase A: depthwise, thread owns channel cl, 16 pixels
        {
            float w9[9];
            #pragma unroll
            for (int j = 0; j < 9; j++) w9[j] = wd[(c0+cl)*9 + j];
            #pragma unroll
            for (int i = 0; i < 16; i++) {
                int p = px16 + 16*i;
                int lx = p & 63, ly = p >> 6;
                const float* tb = it + cl*408 + ly*68 + lx;
                float d;
                d = tb[0]   * w9[0];
                d = fmaf(tb[1],   w9[1], d); d = fmaf(tb[2],   w9[2], d);
                d = fmaf(tb[68],  w9[3], d); d = fmaf(tb[69],  w9[4], d);
                d = fmaf(tb[70],  w9[5], d); d = fmaf(tb[136], w9[6], d);
                d = fmaf(tb[137], w9[7], d); d = fmaf(tb[138], w9[8], d);
                dwb[cl*DWB_STRIDE + p] = d;
            }
        }
        __syncthreads();
        // phase B: 16 k-steps of register-tiled GEMM
        #pragma unroll 4
        for (int kk = 0; kk < 16; kk++) {
            float4 xv = *(const float4*)(dwb + kk*DWB_STRIDE + 4*pg);
            unsigned long long x0 = pack2(xv.x, xv.x);
            unsigned long long x1 = pack2(xv.y, xv.y);
            unsigned long long x2 = pack2(xv.z, xv.z);
            unsigned long long x3 = pack2(xv.w, xv.w);
            const ulonglong2* wr = (const ulonglong2*)(wp + (c0+kk)*80 + 20*po);
            #pragma unroll
            for (int q2 = 0; q2 < 5; q2++) {
                ulonglong2 w = wr[q2];
                ffma2(acc[     2*q2], x0, w.x); ffma2(acc[     2*q2+1], x0, w.y);
                ffma2(acc[10 + 2*q2], x1, w.x); ffma2(acc[10 + 2*q2+1], x1, w.y);
                ffma2(acc[20 + 2*q2], x2, w.x); ffma2(acc[20 + 2*q2+1], x2, w.y);
                ffma2(acc[30 + 2*q2], x3, w.x); ffma2(acc[30 + 2*q2+1], x3, w.y);
            }
        }
    }

    // epilogue: 20 channels x 4 contiguous pixels, float4 stores
    const int lx0 = (4*pg) & 63, ly = pg >> 4;
    const size_t gpix = (size_t)(gy0 + ly) * WW + gx0 + lx0;
    float* ob = out + ((size_t)b*82 + 20*po) * HWW + gpix;
    #pragma unroll
    for (int j = 0; j < 10; j++) {
        float2 f0 = unpack2(acc[j]),    f1 = unpack2(acc[10+j]);
        float2 f2 = unpack2(acc[20+j]), f3 = unpack2(acc[30+j]);
        float4 e = make_float4(fmaxf(f0.x,0.f), fmaxf(f1.x,0.f), fmaxf(f2.x,0.f), fmaxf(f3.x,0.f));
        float4 o = make_float4(fmaxf(f0.y,0.f), fmaxf(f1.y,0.f), fmaxf(f2.y,0.f), fmaxf(f3.y,0.f));
        *(float4*)(ob + (size_t)(2*j)   * HWW) = e;
        *(float4*)(ob + (size_t)(2*j+1) * HWW) = o;
    }
    if (po < 2) {   // flow passthrough ch 80/81
        float4 fv = *(const float4*)(flow + ((size_t)b*2 + po)*HWW + gpix);
        *(float4*)(out + ((size_t)b*82 + 80 + po)*HWW + gpix) = fv;
    }
}

// ---------------- launch ----------------------------------------------------------
extern "C" void kernel_launch(void* const* d_in, const int* in_sizes, int n_in,
                              void* d_out, int out_size) {
    const float* flow = (const float*)d_in[0];
    const float* corr = (const float*)d_in[1];
    const float* Wc1  = (const float*)d_in[2];
    const float* bc1  = (const float*)d_in[3];
    const float* Wf1  = (const float*)d_in[4];
    const float* bf1  = (const float*)d_in[5];
    const float* Wf2  = (const float*)d_in[6];
    const float* bf2  = (const float*)d_in[7];
    const float* Wd   = (const float*)d_in[8];
    const float* Wp   = (const float*)d_in[9];
    const float* bp   = (const float*)d_in[10];
    float* out = (float*)d_out;

    const size_t cor_smem  = (size_t)(CP*96 + 96 + 2*KC*256) * sizeof(float);   // ~130 KB
    const size_t dwpw_smem = (size_t)(10240 + 1152 + 80 + 6528 + 16*DWB_STRIDE) * sizeof(float);
    cudaFuncSetAttribute(cor_kernel,  cudaFuncAttributeMaxDynamicSharedMemorySize, (int)cor_smem);
    cudaFuncSetAttribute(dwpw_kernel, cudaFuncAttributeMaxDynamicSharedMemorySize, (int)dwpw_smem);

    quant_kernel<<<5, 256>>>(Wc1, Wf1, Wf2, Wd, Wp);
    cor_kernel<<<NPIX/256, 256, cor_smem>>>(corr, bc1);
    flo_kernel<<<NPIX/256, 256>>>(flow, bf1, bf2);
    dwpw_kernel<<<NPIX/256, 256, dwpw_smem>>>(flow, bp, out);
}

// round 5
// speedup vs baseline: 2.1539x; 2.1539x over previous
#include <cuda_runtime.h>
#include <cstdint>

#define BB 16
#define HH 96
#define WW 128
#define HWW (HH*WW)          // 12288
#define NPIX (BB*HWW)        // 196608
#define CP 196
#define PH 98                // padded rows   (y+1)
#define PWS 136              // padded stride (x+4)
#define PPL (PH*PWS)         // 13328 floats / channel plane

// ---------------- packed-f32x2 helpers -----------------------------------------
__device__ __forceinline__ unsigned long long pack2(float x, float y) {
    unsigned long long r;
    asm("mov.b64 %0, {%1, %2};" : "=l"(r) : "f"(x), "f"(y));
    return r;
}
__device__ __forceinline__ void ffma2(unsigned long long& acc,
                                      unsigned long long a, unsigned long long b) {
    asm("fma.rn.f32x2 %0, %1, %2, %0;" : "+l"(acc) : "l"(a), "l"(b));
}
__device__ __forceinline__ float2 unpack2(unsigned long long v) {
    float2 f;
    asm("mov.b64 {%0, %1}, %2;" : "=f"(f.x), "=f"(f.y) : "l"(v));
    return f;
}
__device__ __forceinline__ void cp16(uint32_t dst, const void* src) {
    asm volatile("cp.async.cg.shared.global [%0], [%1], 16;" :: "r"(dst), "l"(src));
}

// ---------------- device scratch ------------------------------------------------
__device__ __align__(16) float g_Wc1q[CP*96];     // [k][96]
__device__ __align__(16) float g_Wf1q[64*2];
__device__ __align__(16) float g_Wf2q[64*32];     // [k][32]
__device__ __align__(16) float g_Wdq[128*9];      // [c][9]
__device__ __align__(16) float g_Wpq[128*80];     // [c][80]
// padded activations: zero-initialized BSS; borders NEVER written -> stay zero.
__device__ __align__(16) float g_cfp[(size_t)BB*128*PPL];

// ---------------- 1) per-tensor int8 symmetric fake quant ------------------------
__global__ void quant_kernel(const float* __restrict__ Wc1,
                             const float* __restrict__ Wf1,
                             const float* __restrict__ Wf2,
                             const float* __restrict__ Wd,
                             const float* __restrict__ Wp) {
    __shared__ float red[256];
    __shared__ float s_scale;
    int t = blockIdx.x;
    const float* src; int n;
    if      (t == 0) { src = Wc1; n = 96*CP;  }
    else if (t == 1) { src = Wf1; n = 64*2;   }
    else if (t == 2) { src = Wf2; n = 32*64;  }
    else if (t == 3) { src = Wd;  n = 128*9;  }
    else             { src = Wp;  n = 80*128; }

    float m = 0.f;
    for (int i = threadIdx.x; i < n; i += 256) m = fmaxf(m, fabsf(src[i]));
    red[threadIdx.x] = m;
    __syncthreads();
    for (int s = 128; s > 0; s >>= 1) {
        if (threadIdx.x < s) red[threadIdx.x] = fmaxf(red[threadIdx.x], red[threadIdx.x+s]);
        __syncthreads();
    }
    if (threadIdx.x == 0) s_scale = fmaxf(red[0], 1e-8f) / 127.f;
    __syncthreads();
    float sc = s_scale;

    for (int i = threadIdx.x; i < n; i += 256) {
        float q = rintf(src[i] / sc);
        q = fminf(fmaxf(q, -127.f), 127.f) * sc;
        if      (t == 0) { int o = i / CP,  k = i % CP; g_Wc1q[k*96 + o] = q; }
        else if (t == 1) g_Wf1q[i] = q;
        else if (t == 2) { int o = i / 64,  k = i % 64; g_Wf2q[k*32 + o] = q; }
        else if (t == 3) g_Wdq[i]  = q;
        else             { int o = i / 128, c = i % 128; g_Wpq[c*80 + o] = q; }
    }
}

// ---------------- 2) corr 1x1 196->96 : register-tiled GEMM ----------------------
// grid (768, 2): 256 pixels/block, 48 output channels per blockIdx.y half.
// Thread: 4 pixels x 12 channels. smem ~93 KB -> 2 blocks/SM.
#define KC 28
#define NCHK 7
__global__ __launch_bounds__(256) void cor_kernel(const float* __restrict__ corr,
                                                  const float* __restrict__ bc1) {
    extern __shared__ __align__(16) float sm[];
    float* Ws = sm;                    // [196][48]
    float* bs = Ws + CP*48;            // 48
    float* Xs = bs + 48;               // [2][28][256]

    const int tid = threadIdx.x;
    const int co  = blockIdx.y * 48;
    for (int i = tid; i < CP*48; i += 256) {
        int k = i / 48, j = i % 48;
        Ws[i] = g_Wc1q[k*96 + co + j];
    }
    if (tid < 48) bs[tid] = bc1[co + tid];

    const int pix0 = blockIdx.x * 256;
    const int b = pix0 / HWW, hw0 = pix0 % HWW;
    const float* cbase = corr + (size_t)b * CP * HWW + hw0;

    uint32_t xs_s = (uint32_t)__cvta_generic_to_shared(Xs);

    auto issue = [&](int c, int buf) {
        int e = tid;
        #pragma unroll
        for (int j = 0; j < 7; j++) {          // 7*256 = 1792 float4 = 28x256 floats
            int kk = e >> 6, off = e & 63;
            cp16(xs_s + (uint32_t)(((buf*KC + kk)*256 + off*4)*4),
                 cbase + (size_t)(c*KC + kk) * HWW + off*4);
            e += 256;
        }
        asm volatile("cp.async.commit_group;");
    };

    issue(0, 0);
    __syncthreads();   // Ws/bs visible

    const int po = tid >> 6, pg = tid & 63;    // 4 output-groups x 64 pixel-groups

    unsigned long long acc[24];                // [p=4][q=6] channel pairs
    #pragma unroll
    for (int q = 0; q < 6; q++) {
        unsigned long long bv = pack2(bs[12*po + 2*q], bs[12*po + 2*q + 1]);
        acc[q] = bv; acc[6+q] = bv; acc[12+q] = bv; acc[18+q] = bv;
    }

    for (int c = 0; c < NCHK; c++) {
        if (c + 1 < NCHK) {
            issue(c + 1, (c + 1) & 1);
            asm volatile("cp.async.wait_group 1;");
        } else {
            asm volatile("cp.async.wait_group 0;");
        }
        __syncthreads();
        const float4* xsb = (const float4*)(Xs + (c & 1) * KC * 256);
        const float*  wrb = Ws + c * KC * 48 + 12 * po;
        #pragma unroll 4
        for (int kk = 0; kk < KC; kk++) {
            float4 xv = xsb[kk*64 + pg];
            unsigned long long x0 = pack2(xv.x, xv.x);
            unsigned long long x1 = pack2(xv.y, xv.y);
            unsigned long long x2 = pack2(xv.z, xv.z);
            unsigned long long x3 = pack2(xv.w, xv.w);
            const ulonglong2* wr = (const ulonglong2*)(wrb + kk*48);
            #pragma unroll
            for (int q2 = 0; q2 < 3; q2++) {
                ulonglong2 w = wr[q2];
                ffma2(acc[     2*q2], x0, w.x); ffma2(acc[     2*q2+1], x0, w.y);
                ffma2(acc[ 6 + 2*q2], x1, w.x); ffma2(acc[ 6 + 2*q2+1], x1, w.y);
                ffma2(acc[12 + 2*q2], x2, w.x); ffma2(acc[12 + 2*q2+1], x2, w.y);
                ffma2(acc[18 + 2*q2], x3, w.x); ffma2(acc[18 + 2*q2+1], x3, w.y);
            }
        }
        __syncthreads();   // buffer reuse fence
    }

    const int hw = hw0 + 4*pg;
    const int y = hw >> 7, x = hw & 127;
    float* ob = g_cfp + ((size_t)(b*128 + co + 12*po) * PH + (y+1)) * PWS + x + 4;
    #pragma unroll
    for (int j = 0; j < 6; j++) {
        float2 f0 = unpack2(acc[j]),    f1 = unpack2(acc[6+j]);
        float2 f2 = unpack2(acc[12+j]), f3 = unpack2(acc[18+j]);
        float4 e = make_float4(fmaxf(f0.x,0.f), fmaxf(f1.x,0.f), fmaxf(f2.x,0.f), fmaxf(f3.x,0.f));
        float4 o = make_float4(fmaxf(f0.y,0.f), fmaxf(f1.y,0.f), fmaxf(f2.y,0.f), fmaxf(f3.y,0.f));
        *(float4*)(ob + (size_t)(2*j)   * PPL) = e;
        *(float4*)(ob + (size_t)(2*j+1) * PPL) = o;
    }
}

// ---------------- 3) flow 1x1 chain 2->64->32 + relu (channels 96..127) ----------
__global__ __launch_bounds__(256) void flo_kernel(const float* __restrict__ flow,
                                                  const float* __restrict__ bf1,
                                                  const float* __restrict__ bf2) {
    __shared__ __align__(16) float w1[128];
    __shared__ __align__(16) float w2[64*32];
    __shared__ float b1[64], b2[32];
    for (int i = threadIdx.x; i < 128;  i += 256) w1[i] = g_Wf1q[i];
    for (int i = threadIdx.x; i < 64;   i += 256) b1[i] = bf1[i];
    for (int i = threadIdx.x; i < 2048; i += 256) w2[i] = g_Wf2q[i];
    for (int i = threadIdx.x; i < 32;   i += 256) b2[i] = bf2[i];
    __syncthreads();

    int p  = blockIdx.x * 256 + threadIdx.x;
    int b  = p / HWW, hw = p % HWW;
    float fx = flow[(size_t)b * 2 * HWW + hw];
    float fy = flow[(size_t)b * 2 * HWW + HWW + hw];

    unsigned long long acc[16];
    #pragma unroll
    for (int q = 0; q < 16; q++) acc[q] = pack2(b2[2*q], b2[2*q+1]);

    #pragma unroll 4
    for (int j = 0; j < 64; j++) {
        float h = fmaxf(fmaf(fx, w1[2*j], fmaf(fy, w1[2*j+1], b1[j])), 0.f);
        unsigned long long hh = pack2(h, h);
        const ulonglong2* wv = reinterpret_cast<const ulonglong2*>(w2 + j*32);
        #pragma unroll
        for (int q = 0; q < 8; q++) {
            ulonglong2 a = wv[q];
            ffma2(acc[2*q],   hh, a.x);
            ffma2(acc[2*q+1], hh, a.y);
        }
    }

    const int y = hw >> 7, x = hw & 127;
    float* obase = g_cfp + ((size_t)(b*128 + 96) * PH + (y+1)) * PWS + x + 4;
    #pragma unroll
    for (int q = 0; q < 16; q++) {
        float2 f = unpack2(acc[q]);
        obase[(size_t)(2*q)   * PPL] = fmaxf(f.x, 0.f);
        obase[(size_t)(2*q+1) * PPL] = fmaxf(f.y, 0.f);
    }
}

// ---------------- 4) fused dw3x3 + pw 128->80, dw inline in registers ------------
// grid (384, 2): pixel tile 64w x 8h (512 px), 40 output channels per y-half.
// 128 threads; thread owns 1 column x 4 vertical pixels x 40 outputs.
#define O_HALF 40
__global__ __launch_bounds__(128) void dwpw_kernel(const float* __restrict__ flow,
                                                   const float* __restrict__ bp,
                                                   float* __restrict__ out) {
    extern __shared__ __align__(16) float sm2[];
    float* wph = sm2;              // [128][40]  = 5120
    float* wd  = wph + 5120;       // [128][9]   = 1152
    float* bph = wd + 1152;        // 40
    float* it  = bph + 40;         // [16][10][72] = 11520

    const int tid = threadIdx.x;
    const int o0  = blockIdx.y * O_HALF;
    for (int i = tid; i < 5120; i += 128) wph[i] = g_Wpq[(i/40)*80 + o0 + (i%40)];
    for (int i = tid; i < 1152; i += 128) wd[i] = g_Wdq[i];
    if (tid < 40) bph[tid] = bp[o0 + tid];

    const int blk = blockIdx.x;              // 384 pixel tiles
    const int b = blk / 24, t = blk % 24;
    const int gy0 = (t >> 1) * 8, gx0 = (t & 1) * 64;
    const int c = tid & 63, rg = tid >> 6;   // column 0..63, row-group 0..1

    __syncthreads();                          // bph/wph/wd visible

    unsigned long long acc[80];               // [p=4][q=20] channel pairs
    #pragma unroll
    for (int q = 0; q < 20; q++) {
        unsigned long long bv = pack2(bph[2*q], bph[2*q+1]);
        acc[q] = bv; acc[20+q] = bv; acc[40+q] = bv; acc[60+q] = bv;
    }

    const float* cfb = g_cfp + (size_t)b * 128 * PPL;
    uint32_t it_s = (uint32_t)__cvta_generic_to_shared(it);

    for (int c0 = 0; c0 < 128; c0 += 16) {
        __syncthreads();                      // previous chunk consumed
        {   // unconditional, aligned async halo load: 16 ch x 10 rows x 18 float4
            const float* srcbase = cfb + (size_t)c0 * PPL + gy0 * PWS + gx0;
            #pragma unroll
            for (int j = 0; j < 23; j++) {
                int idx = tid + j*128;
                if (idx < 2880) {
                    int cl = idx / 180, rem = idx % 180;
                    int ry = rem / 18,  rx  = rem % 18;
                    cp16(it_s + (uint32_t)((cl*720 + ry*72 + rx*4)*4),
                         srcbase + (size_t)cl*PPL + ry*PWS + rx*4);
                }
            }
            asm volatile("cp.async.commit_group;");
            asm volatile("cp.async.wait_group 0;");
        }
        __syncthreads();

        #pragma unroll 1
        for (int kk = 0; kk < 16; kk++) {
            const float* tb = it + kk*720 + (rg*4)*72 + c + 3;
            float w9[9];
            #pragma unroll
            for (int j = 0; j < 9; j++) w9[j] = wd[(c0+kk)*9 + j];
            float v[6][3];
            #pragma unroll
            for (int r = 0; r < 6; r++) {
                v[r][0] = tb[r*72];
                v[r][1] = tb[r*72 + 1];
                v[r][2] = tb[r*72 + 2];
            }
            unsigned long long dd[4];
            #pragma unroll
            for (int p = 0; p < 4; p++) {
                float d = v[p][0] * w9[0];
                d = fmaf(v[p][1],   w9[1], d);
                d = fmaf(v[p][2],   w9[2], d);
                d = fmaf(v[p+1][0], w9[3], d);
                d = fmaf(v[p+1][1], w9[4], d);
                d = fmaf(v[p+1][2], w9[5], d);
                d = fmaf(v[p+2][0], w9[6], d);
                d = fmaf(v[p+2][1], w9[7], d);
                d = fmaf(v[p+2][2], w9[8], d);
                dd[p] = pack2(d, d);
            }
            // 40 channels per thread = 10 ulonglong2 (R4 bug was q2<5 here)
            const ulonglong2* wr = (const ulonglong2*)(wph + (c0+kk)*40);
            #pragma unroll
            for (int q2 = 0; q2 < 10; q2++) {
                ulonglong2 w = wr[q2];
                ffma2(acc[     2*q2], dd[0], w.x); ffma2(acc[     2*q2+1], dd[0], w.y);
                ffma2(acc[20 + 2*q2], dd[1], w.x); ffma2(acc[20 + 2*q2+1], dd[1], w.y);
                ffma2(acc[40 + 2*q2], dd[2], w.x); ffma2(acc[40 + 2*q2+1], dd[2], w.y);
                ffma2(acc[60 + 2*q2], dd[3], w.x); ffma2(acc[60 + 2*q2+1], dd[3], w.y);
            }
        }
    }

    // epilogue: coalesced scalar stores (lane = column)
    #pragma unroll
    for (int p = 0; p < 4; p++) {
        const int y = gy0 + rg*4 + p, x = gx0 + c;
        float* ob = out + (size_t)b*82*HWW + y*WW + x;
        #pragma unroll
        for (int q = 0; q < 20; q++) {
            float2 f = unpack2(acc[p*20 + q]);
            ob[(size_t)(o0 + 2*q)   * HWW] = fmaxf(f.x, 0.f);
            ob[(size_t)(o0 + 2*q+1) * HWW] = fmaxf(f.y, 0.f);
        }
        if (blockIdx.y == 1) {   // flow passthrough ch 80/81
            ob[(size_t)80 * HWW] = flow[((size_t)b*2 + 0)*HWW + y*WW + x];
            ob[(size_t)81 * HWW] = flow[((size_t)b*2 + 1)*HWW + y*WW + x];
        }
    }
}

// ---------------- launch ----------------------------------------------------------
extern "C" void kernel_launch(void* const* d_in, const int* in_sizes, int n_in,
                              void* d_out, int out_size) {
    const float* flow = (const float*)d_in[0];
    const float* corr = (const float*)d_in[1];
    const float* Wc1  = (const float*)d_in[2];
    const float* bc1  = (const float*)d_in[3];
    const float* Wf1  = (const float*)d_in[4];
    const float* bf1  = (const float*)d_in[5];
    const float* Wf2  = (const float*)d_in[6];
    const float* bf2  = (const float*)d_in[7];
    const float* Wd   = (const float*)d_in[8];
    const float* Wp   = (const float*)d_in[9];
    const float* bp   = (const float*)d_in[10];
    float* out = (float*)d_out;

    const size_t cor_smem  = (size_t)(CP*48 + 48 + 2*KC*256) * sizeof(float);      // ~93 KB
    const size_t dwpw_smem = (size_t)(5120 + 1152 + 40 + 16*720) * sizeof(float);  // ~70 KB
    cudaFuncSetAttribute(cor_kernel,  cudaFuncAttributeMaxDynamicSharedMemorySize, (int)cor_smem);
    cudaFuncSetAttribute(dwpw_kernel, cudaFuncAttributeMaxDynamicSharedMemorySize, (int)dwpw_smem);

    quant_kernel<<<5, 256>>>(Wc1, Wf1, Wf2, Wd, Wp);
    dim3 cg(NPIX/256, 2);
    cor_kernel<<<cg, 256, cor_smem>>>(corr, bc1);
    flo_kernel<<<NPIX/256, 256>>>(flow, bf1, bf2);
    dim3 dg(NPIX/512, 2);
    dwpw_kernel<<<dg, 128, dwpw_smem>>>(flow, bp, out);
}

// round 6
// speedup vs baseline: 2.2551x; 1.0470x over previous
#include <cuda_runtime.h>
#include <cstdint>

#define BB 16
#define HH 96
#define WW 128
#define HWW (HH*WW)          // 12288
#define NPIX (BB*HWW)        // 196608
#define CP 196
#define PH 98                // padded rows   (y+1)
#define PWS 136              // padded stride (x+4)
#define PPL (PH*PWS)         // 13328 floats / channel plane

// ---------------- packed-f32x2 helpers -----------------------------------------
__device__ __forceinline__ unsigned long long pack2(float x, float y) {
    unsigned long long r;
    asm("mov.b64 %0, {%1, %2};" : "=l"(r) : "f"(x), "f"(y));
    return r;
}
__device__ __forceinline__ void ffma2(unsigned long long& acc,
                                      unsigned long long a, unsigned long long b) {
    asm("fma.rn.f32x2 %0, %1, %2, %0;" : "+l"(acc) : "l"(a), "l"(b));
}
__device__ __forceinline__ float2 unpack2(unsigned long long v) {
    float2 f;
    asm("mov.b64 {%0, %1}, %2;" : "=f"(f.x), "=f"(f.y) : "l"(v));
    return f;
}
__device__ __forceinline__ void cp16(uint32_t dst, const void* src) {
    asm volatile("cp.async.cg.shared.global [%0], [%1], 16;" :: "r"(dst), "l"(src));
}

// ---------------- device scratch ------------------------------------------------
__device__ __align__(16) float g_Wc1q[CP*96];     // [k][96]
__device__ __align__(16) float g_Wf1q[64*2];
__device__ __align__(16) float g_Wf2q[64*32];     // [k][32]
__device__ __align__(16) float g_Wdq[128*9];      // [c][9]
__device__ __align__(16) float g_Wpq[128*80];     // [c][80]
// padded activations: zero-initialized BSS; borders NEVER written -> stay zero.
__device__ __align__(16) float g_cfp[(size_t)BB*128*PPL];

// ---------------- 1) per-tensor int8 symmetric fake quant ------------------------
__global__ void quant_kernel(const float* __restrict__ Wc1,
                             const float* __restrict__ Wf1,
                             const float* __restrict__ Wf2,
                             const float* __restrict__ Wd,
                             const float* __restrict__ Wp) {
    __shared__ float red[256];
    __shared__ float s_scale;
    int t = blockIdx.x;
    const float* src; int n;
    if      (t == 0) { src = Wc1; n = 96*CP;  }
    else if (t == 1) { src = Wf1; n = 64*2;   }
    else if (t == 2) { src = Wf2; n = 32*64;  }
    else if (t == 3) { src = Wd;  n = 128*9;  }
    else             { src = Wp;  n = 80*128; }

    float m = 0.f;
    for (int i = threadIdx.x; i < n; i += 256) m = fmaxf(m, fabsf(src[i]));
    red[threadIdx.x] = m;
    __syncthreads();
    for (int s = 128; s > 0; s >>= 1) {
        if (threadIdx.x < s) red[threadIdx.x] = fmaxf(red[threadIdx.x], red[threadIdx.x+s]);
        __syncthreads();
    }
    if (threadIdx.x == 0) s_scale = fmaxf(red[0], 1e-8f) / 127.f;
    __syncthreads();
    float sc = s_scale;

    for (int i = threadIdx.x; i < n; i += 256) {
        float q = rintf(src[i] / sc);
        q = fminf(fmaxf(q, -127.f), 127.f) * sc;
        if      (t == 0) { int o = i / CP,  k = i % CP; g_Wc1q[k*96 + o] = q; }
        else if (t == 1) g_Wf1q[i] = q;
        else if (t == 2) { int o = i / 64,  k = i % 64; g_Wf2q[k*32 + o] = q; }
        else if (t == 3) g_Wdq[i]  = q;
        else             { int o = i / 128, c = i % 128; g_Wpq[c*80 + o] = q; }
    }
}

// ---------------- 2) corr 1x1 196->96 : register-tiled GEMM, all 96 ch -----------
// grid 768: 256 pixels/block, ALL 96 output channels (corr read ONCE).
// Thread: 4 pixels x 24 channels (acc 48 ull). smem 104 KB -> 2 blocks/SM.
#define KC 14
#define NCHK 14
__global__ __launch_bounds__(256, 2) void cor_kernel(const float* __restrict__ corr,
                                                     const float* __restrict__ bc1) {
    extern __shared__ __align__(16) float sm[];
    float* Ws = sm;                    // [196][96] = 18816
    float* bs = Ws + CP*96;            // 96
    float* Xs = bs + 96;               // [2][14][256] = 7168

    const int tid = threadIdx.x;
    {
        const float4* wsrc = (const float4*)g_Wc1q;
        float4* wdst = (float4*)Ws;
        #pragma unroll 1
        for (int i = tid; i < CP*96/4; i += 256) wdst[i] = wsrc[i];
        if (tid < 96) bs[tid] = bc1[tid];
    }

    const int pix0 = blockIdx.x * 256;
    const int b = pix0 / HWW, hw0 = pix0 % HWW;
    const float* cbase = corr + (size_t)b * CP * HWW + hw0;

    uint32_t xs_s = (uint32_t)__cvta_generic_to_shared(Xs);

    auto issue = [&](int c, int buf) {
        #pragma unroll
        for (int j = 0; j < 4; j++) {          // 14*64 = 896 float4
            int idx = tid + j*256;
            if (idx < 896) {
                int kk = idx >> 6, off = idx & 63;
                cp16(xs_s + (uint32_t)(((buf*KC + kk)*256 + off*4)*4),
                     cbase + (size_t)(c*KC + kk) * HWW + off*4);
            }
        }
        asm volatile("cp.async.commit_group;");
    };

    issue(0, 0);
    __syncthreads();   // Ws/bs visible

    const int po = tid >> 6, pg = tid & 63;    // 4 ch-groups of 24 x 64 pixel-quads

    unsigned long long acc[48];                // [p=4][jj=12] channel pairs
    #pragma unroll
    for (int jj = 0; jj < 12; jj++) {
        unsigned long long bv = pack2(bs[24*po + 2*jj], bs[24*po + 2*jj + 1]);
        acc[jj] = bv; acc[12+jj] = bv; acc[24+jj] = bv; acc[36+jj] = bv;
    }

    for (int c = 0; c < NCHK; c++) {
        if (c + 1 < NCHK) {
            issue(c + 1, (c + 1) & 1);
            asm volatile("cp.async.wait_group 1;");
        } else {
            asm volatile("cp.async.wait_group 0;");
        }
        __syncthreads();
        const float4* xsb = (const float4*)(Xs + (c & 1) * KC * 256);
        const float*  wrb = Ws + c * KC * 96 + 24 * po;
        #pragma unroll
        for (int kk = 0; kk < KC; kk++) {
            float4 xv = xsb[kk*64 + pg];
            unsigned long long x0 = pack2(xv.x, xv.x);
            unsigned long long x1 = pack2(xv.y, xv.y);
            unsigned long long x2 = pack2(xv.z, xv.z);
            unsigned long long x3 = pack2(xv.w, xv.w);
            const ulonglong2* wr = (const ulonglong2*)(wrb + kk*96);
            #pragma unroll
            for (int q2 = 0; q2 < 6; q2++) {
                ulonglong2 w = wr[q2];
                ffma2(acc[     2*q2], x0, w.x); ffma2(acc[     2*q2+1], x0, w.y);
                ffma2(acc[12 + 2*q2], x1, w.x); ffma2(acc[12 + 2*q2+1], x1, w.y);
                ffma2(acc[24 + 2*q2], x2, w.x); ffma2(acc[24 + 2*q2+1], x2, w.y);
                ffma2(acc[36 + 2*q2], x3, w.x); ffma2(acc[36 + 2*q2+1], x3, w.y);
            }
        }
        __syncthreads();   // buffer reuse fence
    }

    const int hw = hw0 + 4*pg;
    const int y = hw >> 7, x = hw & 127;
    float* ob = g_cfp + ((size_t)(b*128 + 24*po) * PH + (y+1)) * PWS + x + 4;
    #pragma unroll
    for (int jj = 0; jj < 12; jj++) {
        float2 f0 = unpack2(acc[jj]),    f1 = unpack2(acc[12+jj]);
        float2 f2 = unpack2(acc[24+jj]), f3 = unpack2(acc[36+jj]);
        float4 e = make_float4(fmaxf(f0.x,0.f), fmaxf(f1.x,0.f), fmaxf(f2.x,0.f), fmaxf(f3.x,0.f));
        float4 o = make_float4(fmaxf(f0.y,0.f), fmaxf(f1.y,0.f), fmaxf(f2.y,0.f), fmaxf(f3.y,0.f));
        *(float4*)(ob + (size_t)(2*jj)   * PPL) = e;
        *(float4*)(ob + (size_t)(2*jj+1) * PPL) = o;
    }
}

// ---------------- 3) flow 1x1 chain 2->64->32 + relu (channels 96..127) ----------
__global__ __launch_bounds__(256) void flo_kernel(const float* __restrict__ flow,
                                                  const float* __restrict__ bf1,
                                                  const float* __restrict__ bf2) {
    __shared__ __align__(16) float w1[128];
    __shared__ __align__(16) float w2[64*32];
    __shared__ float b1[64], b2[32];
    for (int i = threadIdx.x; i < 128;  i += 256) w1[i] = g_Wf1q[i];
    for (int i = threadIdx.x; i < 64;   i += 256) b1[i] = bf1[i];
    for (int i = threadIdx.x; i < 2048; i += 256) w2[i] = g_Wf2q[i];
    for (int i = threadIdx.x; i < 32;   i += 256) b2[i] = bf2[i];
    __syncthreads();

    int p  = blockIdx.x * 256 + threadIdx.x;
    int b  = p / HWW, hw = p % HWW;
    float fx = flow[(size_t)b * 2 * HWW + hw];
    float fy = flow[(size_t)b * 2 * HWW + HWW + hw];

    unsigned long long acc[16];
    #pragma unroll
    for (int q = 0; q < 16; q++) acc[q] = pack2(b2[2*q], b2[2*q+1]);

    #pragma unroll 4
    for (int j = 0; j < 64; j++) {
        float h = fmaxf(fmaf(fx, w1[2*j], fmaf(fy, w1[2*j+1], b1[j])), 0.f);
        unsigned long long hh = pack2(h, h);
        const ulonglong2* wv = reinterpret_cast<const ulonglong2*>(w2 + j*32);
        #pragma unroll
        for (int q = 0; q < 8; q++) {
            ulonglong2 a = wv[q];
            ffma2(acc[2*q],   hh, a.x);
            ffma2(acc[2*q+1], hh, a.y);
        }
    }

    const int y = hw >> 7, x = hw & 127;
    float* obase = g_cfp + ((size_t)(b*128 + 96) * PH + (y+1)) * PWS + x + 4;
    #pragma unroll
    for (int q = 0; q < 16; q++) {
        float2 f = unpack2(acc[q]);
        obase[(size_t)(2*q)   * PPL] = fmaxf(f.x, 0.f);
        obase[(size_t)(2*q+1) * PPL] = fmaxf(f.y, 0.f);
    }
}

// ---------------- 4) fused dw3x3 + pw 128->80, dw inline, 2px/thread -------------
// grid (384, 2): pixel tile 64w x 8h (512 px), 40 output channels per y-half.
// 256 threads; thread owns 1 column x 2 vertical pixels x 40 outputs.
// 8-channel chunks with double-buffered cp.async halo loads.
#define O_HALF 40
#define ITB 5760    // floats per halo buffer: 8 ch * 10 rows * 72
__global__ __launch_bounds__(256, 2) void dwpw_kernel(const float* __restrict__ flow,
                                                      const float* __restrict__ bp,
                                                      float* __restrict__ out) {
    extern __shared__ __align__(16) float sm2[];
    float* wph = sm2;              // [128][40]  = 5120
    float* wd  = wph + 5120;       // [128][9]   = 1152
    float* bph = wd + 1152;        // 40
    float* it  = bph + 40;         // 2 x [8][10][72] = 11520

    const int tid = threadIdx.x;
    const int o0  = blockIdx.y * O_HALF;
    for (int i = tid; i < 5120; i += 256) wph[i] = g_Wpq[(i/40)*80 + o0 + (i%40)];
    for (int i = tid; i < 1152; i += 256) wd[i] = g_Wdq[i];
    if (tid < 40) bph[tid] = bp[o0 + tid];

    const int blk = blockIdx.x;              // 384 pixel tiles
    const int b = blk / 24, t = blk % 24;
    const int gy0 = (t >> 1) * 8, gx0 = (t & 1) * 64;
    const int c = tid & 63, rg = tid >> 6;   // column 0..63, row-group 0..3

    const float* cfb = g_cfp + (size_t)b * 128 * PPL;
    uint32_t it_s = (uint32_t)__cvta_generic_to_shared(it);

    auto issue = [&](int ch, int buf) {      // 8 ch x 10 rows x 18 float4 = 1440
        const float* srcbase = cfb + (size_t)(ch*8) * PPL + gy0 * PWS + gx0;
        #pragma unroll
        for (int j = 0; j < 6; j++) {
            int idx = tid + j*256;
            if (idx < 1440) {
                int cl = idx / 180, rem = idx % 180;
                int ry = rem / 18,  rx  = rem % 18;
                cp16(it_s + (uint32_t)((buf*ITB + cl*720 + ry*72 + rx*4)*4),
                     srcbase + (size_t)cl*PPL + ry*PWS + rx*4);
            }
        }
        asm volatile("cp.async.commit_group;");
    };

    __syncthreads();                          // weights visible

    unsigned long long acc[40];               // [p=2][q=20] channel pairs
    #pragma unroll
    for (int q = 0; q < 20; q++) {
        unsigned long long bv = pack2(bph[2*q], bph[2*q+1]);
        acc[q] = bv; acc[20+q] = bv;
    }

    issue(0, 0);

    for (int ch = 0; ch < 16; ch++) {
        if (ch + 1 < 16) {
            issue(ch + 1, (ch + 1) & 1);
            asm volatile("cp.async.wait_group 1;");
        } else {
            asm volatile("cp.async.wait_group 0;");
        }
        __syncthreads();                      // chunk ch data visible
        const float* itb = it + (ch & 1) * ITB;

        #pragma unroll
        for (int kk = 0; kk < 8; kk++) {
            const float* tb = itb + kk*720 + (rg*2)*72 + c + 3;
            const float* w9 = wd + (ch*8 + kk)*9;
            float d0, d1;
            {   // rolling-row depthwise: 3 live activation regs
                float a0 = tb[0],   a1 = tb[1],   a2 = tb[2];
                d0 = fmaf(a2, w9[2], fmaf(a1, w9[1], a0 * w9[0]));
                a0 = tb[72];  a1 = tb[73];  a2 = tb[74];
                d0 = fmaf(a0, w9[3], d0); d0 = fmaf(a1, w9[4], d0); d0 = fmaf(a2, w9[5], d0);
                d1 = fmaf(a2, w9[2], fmaf(a1, w9[1], a0 * w9[0]));
                a0 = tb[144]; a1 = tb[145]; a2 = tb[146];
                d0 = fmaf(a0, w9[6], d0); d0 = fmaf(a1, w9[7], d0); d0 = fmaf(a2, w9[8], d0);
                d1 = fmaf(a0, w9[3], d1); d1 = fmaf(a1, w9[4], d1); d1 = fmaf(a2, w9[5], d1);
                a0 = tb[216]; a1 = tb[217]; a2 = tb[218];
                d1 = fmaf(a0, w9[6], d1); d1 = fmaf(a1, w9[7], d1); d1 = fmaf(a2, w9[8], d1);
            }
            unsigned long long dd0 = pack2(d0, d0);
            unsigned long long dd1 = pack2(d1, d1);
            const ulonglong2* wr = (const ulonglong2*)(wph + (ch*8 + kk)*40);
            #pragma unroll
            for (int q2 = 0; q2 < 10; q2++) {
                ulonglong2 w = wr[q2];
                ffma2(acc[     2*q2], dd0, w.x); ffma2(acc[     2*q2+1], dd0, w.y);
                ffma2(acc[20 + 2*q2], dd1, w.x); ffma2(acc[20 + 2*q2+1], dd1, w.y);
            }
        }
        __syncthreads();                      // buffer consumed -> reusable
    }

    // epilogue: coalesced scalar stores (lane = column)
    #pragma unroll
    for (int p = 0; p < 2; p++) {
        const int y = gy0 + rg*2 + p, x = gx0 + c;
        float* ob = out + (size_t)b*82*HWW + y*WW + x;
        #pragma unroll
        for (int q = 0; q < 20; q++) {
            float2 f = unpack2(acc[p*20 + q]);
            ob[(size_t)(o0 + 2*q)   * HWW] = fmaxf(f.x, 0.f);
            ob[(size_t)(o0 + 2*q+1) * HWW] = fmaxf(f.y, 0.f);
        }
        if (blockIdx.y == 1) {   // flow passthrough ch 80/81
            ob[(size_t)80 * HWW] = flow[((size_t)b*2 + 0)*HWW + y*WW + x];
            ob[(size_t)81 * HWW] = flow[((size_t)b*2 + 1)*HWW + y*WW + x];
        }
    }
}

// ---------------- launch ----------------------------------------------------------
extern "C" void kernel_launch(void* const* d_in, const int* in_sizes, int n_in,
                              void* d_out, int out_size) {
    const float* flow = (const float*)d_in[0];
    const float* corr = (const float*)d_in[1];
    const float* Wc1  = (const float*)d_in[2];
    const float* bc1  = (const float*)d_in[3];
    const float* Wf1  = (const float*)d_in[4];
    const float* bf1  = (const float*)d_in[5];
    const float* Wf2  = (const float*)d_in[6];
    const float* bf2  = (const float*)d_in[7];
    const float* Wd   = (const float*)d_in[8];
    const float* Wp   = (const float*)d_in[9];
    const float* bp   = (const float*)d_in[10];
    float* out = (float*)d_out;

    const size_t cor_smem  = (size_t)(CP*96 + 96 + 2*KC*256) * sizeof(float);      // ~102 KB
    const size_t dwpw_smem = (size_t)(5120 + 1152 + 40 + 2*ITB) * sizeof(float);   // ~70 KB
    cudaFuncSetAttribute(cor_kernel,  cudaFuncAttributeMaxDynamicSharedMemorySize, (int)cor_smem);
    cudaFuncSetAttribute(dwpw_kernel, cudaFuncAttributeMaxDynamicSharedMemorySize, (int)dwpw_smem);

    quant_kernel<<<5, 256>>>(Wc1, Wf1, Wf2, Wd, Wp);
    cor_kernel<<<NPIX/256, 256, cor_smem>>>(corr, bc1);
    flo_kernel<<<NPIX/256, 256>>>(flow, bf1, bf2);
    dim3 dg(NPIX/512, 2);
    dwpw_kernel<<<dg, 256, dwpw_smem>>>(flow, bp, out);
}

// round 8
// speedup vs baseline: 2.3611x; 1.0470x over previous
#include <cuda_runtime.h>
#include <cstdint>

#define BB 16
#define HH 96
#define WW 128
#define HWW (HH*WW)          // 12288
#define NPIX (BB*HWW)        // 196608
#define CP 196
#define PH 98                // padded rows   (y+1)
#define PWS 136              // padded stride (x+4)
#define PPL (PH*PWS)         // 13328 floats / channel plane

// ---------------- packed-f32x2 helpers -----------------------------------------
__device__ __forceinline__ unsigned long long pack2(float x, float y) {
    unsigned long long r;
    asm("mov.b64 %0, {%1, %2};" : "=l"(r) : "f"(x), "f"(y));
    return r;
}
__device__ __forceinline__ void ffma2(unsigned long long& acc,
                                      unsigned long long a, unsigned long long b) {
    asm("fma.rn.f32x2 %0, %1, %2, %0;" : "+l"(acc) : "l"(a), "l"(b));
}
__device__ __forceinline__ float2 unpack2(unsigned long long v) {
    float2 f;
    asm("mov.b64 {%0, %1}, %2;" : "=f"(f.x), "=f"(f.y) : "l"(v));
    return f;
}
__device__ __forceinline__ void cp16(uint32_t dst, const void* src) {
    asm volatile("cp.async.cg.shared.global [%0], [%1], 16;" :: "r"(dst), "l"(src));
}

// ---------------- device scratch ------------------------------------------------
__device__ __align__(16) float g_Wc1q[CP*96];     // [k][96]
__device__ __align__(16) float g_Wf1q[64*2];
__device__ __align__(16) float g_Wf2q[64*32];     // [k][32]
__device__ __align__(16) float g_Wdq[128*12];     // [c][12] (9 taps + 3 zero pad, BSS=0)
__device__ __align__(16) float g_Wpq[128*80];     // [c][80]
// padded activations: zero-initialized BSS; borders NEVER written -> stay zero.
__device__ __align__(16) float g_cfp[(size_t)BB*128*PPL];

// ---------------- 1) per-tensor int8 symmetric fake quant ------------------------
__global__ void quant_kernel(const float* __restrict__ Wc1,
                             const float* __restrict__ Wf1,
                             const float* __restrict__ Wf2,
                             const float* __restrict__ Wd,
                             const float* __restrict__ Wp) {
    __shared__ float red[256];
    __shared__ float s_scale;
    int t = blockIdx.x;
    const float* src; int n;
    if      (t == 0) { src = Wc1; n = 96*CP;  }
    else if (t == 1) { src = Wf1; n = 64*2;   }
    else if (t == 2) { src = Wf2; n = 32*64;  }
    else if (t == 3) { src = Wd;  n = 128*9;  }
    else             { src = Wp;  n = 80*128; }

    float m = 0.f;
    for (int i = threadIdx.x; i < n; i += 256) m = fmaxf(m, fabsf(src[i]));
    red[threadIdx.x] = m;
    __syncthreads();
    for (int s = 128; s > 0; s >>= 1) {
        if (threadIdx.x < s) red[threadIdx.x] = fmaxf(red[threadIdx.x], red[threadIdx.x+s]);
        __syncthreads();
    }
    if (threadIdx.x == 0) s_scale = fmaxf(red[0], 1e-8f) / 127.f;
    __syncthreads();
    float sc = s_scale;

    for (int i = threadIdx.x; i < n; i += 256) {
        float q = rintf(src[i] / sc);
        q = fminf(fmaxf(q, -127.f), 127.f) * sc;
        if      (t == 0) { int o = i / CP,  k = i % CP; g_Wc1q[k*96 + o] = q; }
        else if (t == 1) g_Wf1q[i] = q;
        else if (t == 2) { int o = i / 64,  k = i % 64; g_Wf2q[k*32 + o] = q; }
        else if (t == 3) { int c = i / 9,   j = i % 9;  g_Wdq[c*12 + j] = q; }
        else             { int o = i / 128, c = i % 128; g_Wpq[c*80 + o] = q; }
    }
}

// ---------------- 2) fused cor (1x1 196->96) + flo (2->64->32) -------------------
// blocks 0..767   : cor, 256 pixels, all 96 channels, thread = 4 px x 24 ch
// blocks 768..1535: flo, 256 pixels, thread = 1 px x 32 ch
#define KC 14
#define NCHK 14
__global__ __launch_bounds__(256, 2) void corflo_kernel(const float* __restrict__ corr,
                                                        const float* __restrict__ bc1,
                                                        const float* __restrict__ flow,
                                                        const float* __restrict__ bf1,
                                                        const float* __restrict__ bf2) {
    extern __shared__ __align__(16) float sm[];
    const int tid = threadIdx.x;

    if (blockIdx.x >= 768) {
        // ---------------- flo path ----------------
        float* w1 = sm;            // 128
        float* b1 = sm + 128;      // 64
        float* w2 = sm + 192;      // 2048 [k][32]
        float* b2 = sm + 2240;     // 32
        for (int i = tid; i < 128;  i += 256) w1[i] = g_Wf1q[i];
        for (int i = tid; i < 64;   i += 256) b1[i] = bf1[i];
        for (int i = tid; i < 2048; i += 256) w2[i] = g_Wf2q[i];
        for (int i = tid; i < 32;   i += 256) b2[i] = bf2[i];
        __syncthreads();

        int p  = (blockIdx.x - 768) * 256 + tid;
        int b  = p / HWW, hw = p % HWW;
        float fx = flow[(size_t)b * 2 * HWW + hw];
        float fy = flow[(size_t)b * 2 * HWW + HWW + hw];

        unsigned long long acc[16];
        #pragma unroll
        for (int q = 0; q < 16; q++) acc[q] = pack2(b2[2*q], b2[2*q+1]);

        #pragma unroll 4
        for (int j = 0; j < 64; j++) {
            float h = fmaxf(fmaf(fx, w1[2*j], fmaf(fy, w1[2*j+1], b1[j])), 0.f);
            unsigned long long hh = pack2(h, h);
            const ulonglong2* wv = reinterpret_cast<const ulonglong2*>(w2 + j*32);
            #pragma unroll
            for (int q = 0; q < 8; q++) {
                ulonglong2 a = wv[q];
                ffma2(acc[2*q],   hh, a.x);
                ffma2(acc[2*q+1], hh, a.y);
            }
        }

        const int y = hw >> 7, x = hw & 127;
        float* obase = g_cfp + ((size_t)(b*128 + 96) * PH + (y+1)) * PWS + x + 4;
        #pragma unroll
        for (int q = 0; q < 16; q++) {
            float2 f = unpack2(acc[q]);
            obase[(size_t)(2*q)   * PPL] = fmaxf(f.x, 0.f);
            obase[(size_t)(2*q+1) * PPL] = fmaxf(f.y, 0.f);
        }
        return;
    }

    // ---------------- cor path ----------------
    float* Ws = sm;                    // [196][96] = 18816
    float* bs = Ws + CP*96;            // 96
    float* Xs = bs + 96;               // [2][14][256] = 7168

    {
        const float4* wsrc = (const float4*)g_Wc1q;
        float4* wdst = (float4*)Ws;
        #pragma unroll 1
        for (int i = tid; i < CP*96/4; i += 256) wdst[i] = wsrc[i];
        if (tid < 96) bs[tid] = bc1[tid];
    }

    const int pix0 = blockIdx.x * 256;
    const int b = pix0 / HWW, hw0 = pix0 % HWW;
    const float* cbase = corr + (size_t)b * CP * HWW + hw0;

    uint32_t xs_s = (uint32_t)__cvta_generic_to_shared(Xs);

    auto issue = [&](int c, int buf) {
        #pragma unroll
        for (int j = 0; j < 4; j++) {          // 14*64 = 896 float4
            int idx = tid + j*256;
            if (idx < 896) {
                int kk = idx >> 6, off = idx & 63;
                cp16(xs_s + (uint32_t)(((buf*KC + kk)*256 + off*4)*4),
                     cbase + (size_t)(c*KC + kk) * HWW + off*4);
            }
        }
        asm volatile("cp.async.commit_group;");
    };

    issue(0, 0);
    __syncthreads();   // Ws/bs visible

    const int po = tid >> 6, pg = tid & 63;    // 4 ch-groups of 24 x 64 pixel-quads

    unsigned long long acc[48];                // [p=4][jj=12] channel pairs
    #pragma unroll
    for (int jj = 0; jj < 12; jj++) {
        unsigned long long bv = pack2(bs[24*po + 2*jj], bs[24*po + 2*jj + 1]);
        acc[jj] = bv; acc[12+jj] = bv; acc[24+jj] = bv; acc[36+jj] = bv;
    }

    for (int c = 0; c < NCHK; c++) {
        if (c + 1 < NCHK) {
            issue(c + 1, (c + 1) & 1);
            asm volatile("cp.async.wait_group 1;");
        } else {
            asm volatile("cp.async.wait_group 0;");
        }
        __syncthreads();
        const float4* xsb = (const float4*)(Xs + (c & 1) * KC * 256);
        const float*  wrb = Ws + c * KC * 96 + 24 * po;
        #pragma unroll
        for (int kk = 0; kk < KC; kk++) {
            float4 xv = xsb[kk*64 + pg];
            unsigned long long x0 = pack2(xv.x, xv.x);
            unsigned long long x1 = pack2(xv.y, xv.y);
            unsigned long long x2 = pack2(xv.z, xv.z);
            unsigned long long x3 = pack2(xv.w, xv.w);
            const ulonglong2* wr = (const ulonglong2*)(wrb + kk*96);
            #pragma unroll
            for (int q2 = 0; q2 < 6; q2++) {
                ulonglong2 w = wr[q2];
                ffma2(acc[     2*q2], x0, w.x); ffma2(acc[     2*q2+1], x0, w.y);
                ffma2(acc[12 + 2*q2], x1, w.x); ffma2(acc[12 + 2*q2+1], x1, w.y);
                ffma2(acc[24 + 2*q2], x2, w.x); ffma2(acc[24 + 2*q2+1], x2, w.y);
                ffma2(acc[36 + 2*q2], x3, w.x); ffma2(acc[36 + 2*q2+1], x3, w.y);
            }
        }
        __syncthreads();   // buffer reuse fence
    }

    const int hw = hw0 + 4*pg;
    const int y = hw >> 7, x = hw & 127;
    float* ob = g_cfp + ((size_t)(b*128 + 24*po) * PH + (y+1)) * PWS + x + 4;
    #pragma unroll
    for (int jj = 0; jj < 12; jj++) {
        float2 f0 = unpack2(acc[jj]),    f1 = unpack2(acc[12+jj]);
        float2 f2 = unpack2(acc[24+jj]), f3 = unpack2(acc[36+jj]);
        float4 e = make_float4(fmaxf(f0.x,0.f), fmaxf(f1.x,0.f), fmaxf(f2.x,0.f), fmaxf(f3.x,0.f));
        float4 o = make_float4(fmaxf(f0.y,0.f), fmaxf(f1.y,0.f), fmaxf(f2.y,0.f), fmaxf(f3.y,0.f));
        *(float4*)(ob + (size_t)(2*jj)   * PPL) = e;
        *(float4*)(ob + (size_t)(2*jj+1) * PPL) = o;
    }
}

// ---------------- 3) fused dw3x3 + pw 128->80, dw inline, 2px/thread -------------
// grid (384, 2): pixel tile 64w x 8h (512 px), 40 output channels per y-half.
// 256 threads; thread owns 1 column x 2 vertical pixels x 40 outputs.
// 8-channel chunks with double-buffered cp.async halo loads.
#define O_HALF 40
#define ITB 5760    // floats per halo buffer: 8 ch * 10 rows * 72
__global__ __launch_bounds__(256, 2) void dwpw_kernel(const float* __restrict__ flow,
                                                      const float* __restrict__ bp,
                                                      float* __restrict__ out) {
    extern __shared__ __align__(16) float sm2[];
    float* wph = sm2;              // [128][40]  = 5120
    float* wd  = wph + 5120;       // [128][12]  = 1536 (float4 x3 per channel)
    float* bph = wd + 1536;        // 40
    float* it  = bph + 40;         // 2 x [8][10][72] = 11520

    const int tid = threadIdx.x;
    const int o0  = blockIdx.y * O_HALF;
    for (int i = tid; i < 5120; i += 256) wph[i] = g_Wpq[(i/40)*80 + o0 + (i%40)];
    for (int i = tid; i < 1536/4; i += 256) ((float4*)wd)[i] = ((const float4*)g_Wdq)[i];
    if (tid < 40) bph[tid] = bp[o0 + tid];

    const int blk = blockIdx.x;              // 384 pixel tiles
    const int b = blk / 24, t = blk % 24;
    const int gy0 = (t >> 1) * 8, gx0 = (t & 1) * 64;
    const int c = tid & 63, rg = tid >> 6;   // column 0..63, row-group 0..3

    const float* cfb = g_cfp + (size_t)b * 128 * PPL;
    uint32_t it_s = (uint32_t)__cvta_generic_to_shared(it);

    auto issue = [&](int ch, int buf) {      // 8 ch x 10 rows x 18 float4 = 1440
        const float* srcbase = cfb + (size_t)(ch*8) * PPL + gy0 * PWS + gx0;
        #pragma unroll
        for (int j = 0; j < 6; j++) {
            int idx = tid + j*256;
            if (idx < 1440) {
                int cl = idx / 180, rem = idx % 180;
                int ry = rem / 18,  rx  = rem % 18;
                cp16(it_s + (uint32_t)((buf*ITB + cl*720 + ry*72 + rx*4)*4),
                     srcbase + (size_t)cl*PPL + ry*PWS + rx*4);
            }
        }
        asm volatile("cp.async.commit_group;");
    };

    __syncthreads();                          // weights visible

    unsigned long long acc[40];               // [p=2][q=20] channel pairs
    #pragma unroll
    for (int q = 0; q < 20; q++) {
        unsigned long long bv = pack2(bph[2*q], bph[2*q+1]);
        acc[q] = bv; acc[20+q] = bv;
    }

    issue(0, 0);

    for (int ch = 0; ch < 16; ch++) {
        if (ch + 1 < 16) {
            issue(ch + 1, (ch + 1) & 1);
            asm volatile("cp.async.wait_group 1;");
        } else {
            asm volatile("cp.async.wait_group 0;");
        }
        __syncthreads();                      // chunk ch data visible
        const float* itb = it + (ch & 1) * ITB;

        #pragma unroll
        for (int kk = 0; kk < 8; kk++) {
            const float* tb = itb + kk*720 + (rg*2)*72 + c + 3;
            const float4* w4 = (const float4*)(wd + (ch*8 + kk)*12);
            float4 wa = w4[0], wb = w4[1];
            float  w8 = w4[2].x;
            float d0, d1;
            {   // rolling-row depthwise: taps wa.x..wa.w, wb.x..wb.w, w8
                float a0 = tb[0],   a1 = tb[1],   a2 = tb[2];
                d0 = fmaf(a2, wa.z, fmaf(a1, wa.y, a0 * wa.x));
                a0 = tb[72];  a1 = tb[73];  a2 = tb[74];
                d0 = fmaf(a0, wa.w, d0); d0 = fmaf(a1, wb.x, d0); d0 = fmaf(a2, wb.y, d0);
                d1 = fmaf(a2, wa.z, fmaf(a1, wa.y, a0 * wa.x));
                a0 = tb[144]; a1 = tb[145]; a2 = tb[146];
                d0 = fmaf(a0, wb.z, d0); d0 = fmaf(a1, wb.w, d0); d0 = fmaf(a2, w8, d0);
                d1 = fmaf(a0, wa.w, d1); d1 = fmaf(a1, wb.x, d1); d1 = fmaf(a2, wb.y, d1);
                a0 = tb[216]; a1 = tb[217]; a2 = tb[218];
                d1 = fmaf(a0, wb.z, d1); d1 = fmaf(a1, wb.w, d1); d1 = fmaf(a2, w8, d1);
            }
            unsigned long long dd0 = pack2(d0, d0);
            unsigned long long dd1 = pack2(d1, d1);
            const ulonglong2* wr = (const ulonglong2*)(wph + (ch*8 + kk)*40);
            #pragma unroll
            for (int q2 = 0; q2 < 10; q2++) {
                ulonglong2 w = wr[q2];
                ffma2(acc[     2*q2], dd0, w.x); ffma2(acc[     2*q2+1], dd0, w.y);
                ffma2(acc[20 + 2*q2], dd1, w.x); ffma2(acc[20 + 2*q2+1], dd1, w.y);
            }
        }
        __syncthreads();                      // buffer consumed -> reusable
    }

    // epilogue: coalesced scalar stores (lane = column)
    #pragma unroll
    for (int p = 0; p < 2; p++) {
        const int y = gy0 + rg*2 + p, x = gx0 + c;
        float* ob = out + (size_t)b*82*HWW + y*WW + x;
        #pragma unroll
        for (int q = 0; q < 20; q++) {
            float2 f = unpack2(acc[p*20 + q]);
            ob[(size_t)(o0 + 2*q)   * HWW] = fmaxf(f.x, 0.f);
            ob[(size_t)(o0 + 2*q+1) * HWW] = fmaxf(f.y, 0.f);
        }
        if (blockIdx.y == 1) {   // flow passthrough ch 80/81
            ob[(size_t)80 * HWW] = flow[((size_t)b*2 + 0)*HWW + y*WW + x];
            ob[(size_t)81 * HWW] = flow[((size_t)b*2 + 1)*HWW + y*WW + x];
        }
    }
}

// ---------------- launch ----------------------------------------------------------
extern "C" void kernel_launch(void* const* d_in, const int* in_sizes, int n_in,
                              void* d_out, int out_size) {
    const float* flow = (const float*)d_in[0];
    const float* corr = (const float*)d_in[1];
    const float* Wc1  = (const float*)d_in[2];
    const float* bc1  = (const float*)d_in[3];
    const float* Wf1  = (const float*)d_in[4];
    const float* bf1  = (const float*)d_in[5];
    const float* Wf2  = (const float*)d_in[6];
    const float* bf2  = (const float*)d_in[7];
    const float* Wd   = (const float*)d_in[8];
    const float* Wp   = (const float*)d_in[9];
    const float* bp   = (const float*)d_in[10];
    float* out = (float*)d_out;

    const size_t cor_smem  = (size_t)(CP*96 + 96 + 2*KC*256) * sizeof(float);       // ~102 KB
    const size_t dwpw_smem = (size_t)(5120 + 1536 + 40 + 2*ITB) * sizeof(float);    // ~71 KB
    cudaFuncSetAttribute(corflo_kernel, cudaFuncAttributeMaxDynamicSharedMemorySize, (int)cor_smem);
    cudaFuncSetAttribute(dwpw_kernel,   cudaFuncAttributeMaxDynamicSharedMemorySize, (int)dwpw_smem);

    quant_kernel<<<5, 256>>>(Wc1, Wf1, Wf2, Wd, Wp);
    corflo_kernel<<<1536, 256, cor_smem>>>(corr, bc1, flow, bf1, bf2);
    dim3 dg(NPIX/512, 2);
    dwpw_kernel<<<dg, 256, dwpw_smem>>>(flow, bp, out);
}

// round 9
// speedup vs baseline: 2.5832x; 1.0940x over previous
#include <cuda_runtime.h>
#include <cstdint>

#define BB 16
#define HH 96
#define WW 128
#define HWW (HH*WW)          // 12288
#define NPIX (BB*HWW)        // 196608
#define CP 196
#define PH 98                // padded rows   (y+1)
#define PWS 136              // padded stride (x+4)
#define PPL (PH*PWS)         // 13328 floats / channel plane

// ---------------- packed-f32x2 helpers -----------------------------------------
__device__ __forceinline__ unsigned long long pack2(float x, float y) {
    unsigned long long r;
    asm("mov.b64 %0, {%1, %2};" : "=l"(r) : "f"(x), "f"(y));
    return r;
}
__device__ __forceinline__ void ffma2(unsigned long long& acc,
                                      unsigned long long a, unsigned long long b) {
    asm("fma.rn.f32x2 %0, %1, %2, %0;" : "+l"(acc) : "l"(a), "l"(b));
}
__device__ __forceinline__ float2 unpack2(unsigned long long v) {
    float2 f;
    asm("mov.b64 {%0, %1}, %2;" : "=f"(f.x), "=f"(f.y) : "l"(v));
    return f;
}
__device__ __forceinline__ void cp16(uint32_t dst, const void* src) {
    asm volatile("cp.async.cg.shared.global [%0], [%1], 16;" :: "r"(dst), "l"(src));
}

// ---------------- device scratch ------------------------------------------------
__device__ unsigned g_scmax[5];                   // maxabs bits per tensor
__device__ __align__(16) float g_Wc1q[CP*96];     // [k][96]
__device__ __align__(16) float g_Wf1q[64*2];
__device__ __align__(16) float g_Wf2q[64*32];     // [k][32]
__device__ __align__(16) float g_Wdq[128*12];     // [c][12] (9 taps + 3 zero pad, BSS=0)
__device__ __align__(16) float g_Wpq[128*80];     // [c][80]
// padded activations: zero-initialized BSS; borders NEVER written -> stay zero.
__device__ __align__(16) float g_cfp[(size_t)BB*128*PPL];

// ---------------- 1) quantization: init / reduce / pack ---------------------------
__device__ __forceinline__ void qmap(int bid, int& t, int& start, int& cnt) {
    if      (bid < 32)  { t = 0; start = bid * 588;        cnt = 588;  }  // 32*588=18816
    else if (bid == 32) { t = 1; start = 0;                cnt = 128;  }
    else if (bid == 33) { t = 2; start = 0;                cnt = 2048; }
    else if (bid == 34) { t = 3; start = 0;                cnt = 1152; }
    else                { t = 4; start = (bid - 35) * 2048; cnt = 2048; } // 5*2048=10240
}

__global__ void quant_init() { if (threadIdx.x < 5) g_scmax[threadIdx.x] = 0u; }

__global__ void quant_reduce(const float* __restrict__ Wc1,
                             const float* __restrict__ Wf1,
                             const float* __restrict__ Wf2,
                             const float* __restrict__ Wd,
                             const float* __restrict__ Wp) {
    __shared__ float red[256];
    int t, start, cnt;
    qmap(blockIdx.x, t, start, cnt);
    const float* src = (t==0) ? Wc1 : (t==1) ? Wf1 : (t==2) ? Wf2 : (t==3) ? Wd : Wp;

    float m = 0.f;
    for (int i = threadIdx.x; i < cnt; i += 256) m = fmaxf(m, fabsf(src[start + i]));
    red[threadIdx.x] = m;
    __syncthreads();
    for (int s = 128; s > 0; s >>= 1) {
        if (threadIdx.x < s) red[threadIdx.x] = fmaxf(red[threadIdx.x], red[threadIdx.x+s]);
        __syncthreads();
    }
    if (threadIdx.x == 0) atomicMax(&g_scmax[t], __float_as_uint(red[0]));
}

__global__ void quant_pack(const float* __restrict__ Wc1,
                           const float* __restrict__ Wf1,
                           const float* __restrict__ Wf2,
                           const float* __restrict__ Wd,
                           const float* __restrict__ Wp) {
    int t, start, cnt;
    qmap(blockIdx.x, t, start, cnt);
    const float* src = (t==0) ? Wc1 : (t==1) ? Wf1 : (t==2) ? Wf2 : (t==3) ? Wd : Wp;
    const float sc = fmaxf(__uint_as_float(g_scmax[t]), 1e-8f) / 127.f;

    for (int ii = threadIdx.x; ii < cnt; ii += 256) {
        int i = start + ii;
        float q = rintf(src[i] / sc);
        q = fminf(fmaxf(q, -127.f), 127.f) * sc;
        if      (t == 0) { int o = i / CP,  k = i % CP; g_Wc1q[k*96 + o] = q; }
        else if (t == 1) g_Wf1q[i] = q;
        else if (t == 2) { int o = i / 64,  k = i % 64; g_Wf2q[k*32 + o] = q; }
        else if (t == 3) { int c = i / 9,   j = i % 9;  g_Wdq[c*12 + j] = q; }
        else             { int o = i / 128, c = i % 128; g_Wpq[c*80 + o] = q; }
    }
}

// ---------------- 2) fused cor (1x1 196->96) + flo (2->64->32) -------------------
#define KC 14
#define NCHK 14
__global__ __launch_bounds__(256, 2) void corflo_kernel(const float* __restrict__ corr,
                                                        const float* __restrict__ bc1,
                                                        const float* __restrict__ flow,
                                                        const float* __restrict__ bf1,
                                                        const float* __restrict__ bf2) {
    extern __shared__ __align__(16) float sm[];
    const int tid = threadIdx.x;

    if (blockIdx.x >= 768) {
        // ---------------- flo path ----------------
        float* w1 = sm;            // 128
        float* b1 = sm + 128;      // 64
        float* w2 = sm + 192;      // 2048 [k][32]
        float* b2 = sm + 2240;     // 32
        for (int i = tid; i < 128;  i += 256) w1[i] = g_Wf1q[i];
        for (int i = tid; i < 64;   i += 256) b1[i] = bf1[i];
        for (int i = tid; i < 2048; i += 256) w2[i] = g_Wf2q[i];
        for (int i = tid; i < 32;   i += 256) b2[i] = bf2[i];
        __syncthreads();

        int p  = (blockIdx.x - 768) * 256 + tid;
        int b  = p / HWW, hw = p % HWW;
        float fx = flow[(size_t)b * 2 * HWW + hw];
        float fy = flow[(size_t)b * 2 * HWW + HWW + hw];

        unsigned long long acc[16];
        #pragma unroll
        for (int q = 0; q < 16; q++) acc[q] = pack2(b2[2*q], b2[2*q+1]);

        #pragma unroll 4
        for (int j = 0; j < 64; j++) {
            float h = fmaxf(fmaf(fx, w1[2*j], fmaf(fy, w1[2*j+1], b1[j])), 0.f);
            unsigned long long hh = pack2(h, h);
            const ulonglong2* wv = reinterpret_cast<const ulonglong2*>(w2 + j*32);
            #pragma unroll
            for (int q = 0; q < 8; q++) {
                ulonglong2 a = wv[q];
                ffma2(acc[2*q],   hh, a.x);
                ffma2(acc[2*q+1], hh, a.y);
            }
        }

        const int y = hw >> 7, x = hw & 127;
        float* obase = g_cfp + ((size_t)(b*128 + 96) * PH + (y+1)) * PWS + x + 4;
        #pragma unroll
        for (int q = 0; q < 16; q++) {
            float2 f = unpack2(acc[q]);
            obase[(size_t)(2*q)   * PPL] = fmaxf(f.x, 0.f);
            obase[(size_t)(2*q+1) * PPL] = fmaxf(f.y, 0.f);
        }
        return;
    }

    // ---------------- cor path ----------------
    float* Ws = sm;                    // [196][96] = 18816
    float* bs = Ws + CP*96;            // 96
    float* Xs = bs + 96;               // [2][14][256] = 7168

    {
        const float4* wsrc = (const float4*)g_Wc1q;
        float4* wdst = (float4*)Ws;
        #pragma unroll 1
        for (int i = tid; i < CP*96/4; i += 256) wdst[i] = wsrc[i];
        if (tid < 96) bs[tid] = bc1[tid];
    }

    const int pix0 = blockIdx.x * 256;
    const int b = pix0 / HWW, hw0 = pix0 % HWW;
    const float* cbase = corr + (size_t)b * CP * HWW + hw0;

    uint32_t xs_s = (uint32_t)__cvta_generic_to_shared(Xs);

    auto issue = [&](int c, int buf) {
        #pragma unroll
        for (int j = 0; j < 4; j++) {          // 14*64 = 896 float4
            int idx = tid + j*256;
            if (idx < 896) {
                int kk = idx >> 6, off = idx & 63;
                cp16(xs_s + (uint32_t)(((buf*KC + kk)*256 + off*4)*4),
                     cbase + (size_t)(c*KC + kk) * HWW + off*4);
            }
        }
        asm volatile("cp.async.commit_group;");
    };

    issue(0, 0);
    __syncthreads();   // Ws/bs visible

    const int po = tid >> 6, pg = tid & 63;

    unsigned long long acc[48];                // [p=4][jj=12] channel pairs
    #pragma unroll
    for (int jj = 0; jj < 12; jj++) {
        unsigned long long bv = pack2(bs[24*po + 2*jj], bs[24*po + 2*jj + 1]);
        acc[jj] = bv; acc[12+jj] = bv; acc[24+jj] = bv; acc[36+jj] = bv;
    }

    for (int c = 0; c < NCHK; c++) {
        if (c + 1 < NCHK) {
            issue(c + 1, (c + 1) & 1);
            asm volatile("cp.async.wait_group 1;");
        } else {
            asm volatile("cp.async.wait_group 0;");
        }
        __syncthreads();
        const float4* xsb = (const float4*)(Xs + (c & 1) * KC * 256);
        const float*  wrb = Ws + c * KC * 96 + 24 * po;
        #pragma unroll
        for (int kk = 0; kk < KC; kk++) {
            float4 xv = xsb[kk*64 + pg];
            unsigned long long x0 = pack2(xv.x, xv.x);
            unsigned long long x1 = pack2(xv.y, xv.y);
            unsigned long long x2 = pack2(xv.z, xv.z);
            unsigned long long x3 = pack2(xv.w, xv.w);
            const ulonglong2* wr = (const ulonglong2*)(wrb + kk*96);
            #pragma unroll
            for (int q2 = 0; q2 < 6; q2++) {
                ulonglong2 w = wr[q2];
                ffma2(acc[     2*q2], x0, w.x); ffma2(acc[     2*q2+1], x0, w.y);
                ffma2(acc[12 + 2*q2], x1, w.x); ffma2(acc[12 + 2*q2+1], x1, w.y);
                ffma2(acc[24 + 2*q2], x2, w.x); ffma2(acc[24 + 2*q2+1], x2, w.y);
                ffma2(acc[36 + 2*q2], x3, w.x); ffma2(acc[36 + 2*q2+1], x3, w.y);
            }
        }
        __syncthreads();   // buffer reuse fence
    }

    const int hw = hw0 + 4*pg;
    const int y = hw >> 7, x = hw & 127;
    float* ob = g_cfp + ((size_t)(b*128 + 24*po) * PH + (y+1)) * PWS + x + 4;
    #pragma unroll
    for (int jj = 0; jj < 12; jj++) {
        float2 f0 = unpack2(acc[jj]),    f1 = unpack2(acc[12+jj]);
        float2 f2 = unpack2(acc[24+jj]), f3 = unpack2(acc[36+jj]);
        float4 e = make_float4(fmaxf(f0.x,0.f), fmaxf(f1.x,0.f), fmaxf(f2.x,0.f), fmaxf(f3.x,0.f));
        float4 o = make_float4(fmaxf(f0.y,0.f), fmaxf(f1.y,0.f), fmaxf(f2.y,0.f), fmaxf(f3.y,0.f));
        *(float4*)(ob + (size_t)(2*jj)   * PPL) = e;
        *(float4*)(ob + (size_t)(2*jj+1) * PPL) = o;
    }
}

// ---------------- 3) fused dw3x3 + pw 128->80 : 4px x 20ch per thread ------------
// grid 768: pixel tile 64w x 4h; 256 threads = 64 cols x 4 ch-groups.
// ALL 80 outputs in one block (halo read once). 8-ch chunks, double-buffered.
#define ITB 3456    // floats per halo buffer: 8 ch * 6 rows * 72
__global__ __launch_bounds__(256, 2) void dwpw_kernel(const float* __restrict__ flow,
                                                      const float* __restrict__ bp,
                                                      float* __restrict__ out) {
    extern __shared__ __align__(16) float sm2[];
    float* wph = sm2;              // [128][80]  = 10240
    float* wd  = wph + 10240;      // [128][12]  = 1536
    float* bph = wd + 1536;        // 80
    float* it  = bph + 80;         // 2 x [8][6][72] = 6912

    const int tid = threadIdx.x;
    for (int i = tid; i < 10240/4; i += 256) ((float4*)wph)[i] = ((const float4*)g_Wpq)[i];
    for (int i = tid; i < 1536/4;  i += 256) ((float4*)wd)[i]  = ((const float4*)g_Wdq)[i];
    if (tid < 80) bph[tid] = bp[tid];

    const int blk = blockIdx.x;              // 768 tiles: 16b x 24 y x 2 x
    const int b = blk / 48, t = blk % 48;
    const int gy0 = (t >> 1) * 4, gx0 = (t & 1) * 64;
    const int c = tid & 63, og = tid >> 6;   // column 0..63, ch-group 0..3

    const float* cfb = g_cfp + (size_t)b * 128 * PPL;
    uint32_t it_s = (uint32_t)__cvta_generic_to_shared(it);

    auto issue = [&](int ch, int buf) {      // 8 ch x 6 rows x 18 float4 = 864
        const float* srcbase = cfb + (size_t)(ch*8) * PPL + gy0 * PWS + gx0;
        #pragma unroll
        for (int j = 0; j < 4; j++) {
            int idx = tid + j*256;
            if (idx < 864) {
                int cl = idx / 108, rem = idx % 108;
                int ry = rem / 18,  rx  = rem % 18;
                cp16(it_s + (uint32_t)((buf*ITB + cl*432 + ry*72 + rx*4)*4),
                     srcbase + (size_t)cl*PPL + ry*PWS + rx*4);
            }
        }
        asm volatile("cp.async.commit_group;");
    };

    __syncthreads();                          // weights visible

    unsigned long long acc[40];               // [p=4][q=10] channel pairs
    #pragma unroll
    for (int q = 0; q < 10; q++) {
        unsigned long long bv = pack2(bph[og*20 + 2*q], bph[og*20 + 2*q + 1]);
        acc[q] = bv; acc[10+q] = bv; acc[20+q] = bv; acc[30+q] = bv;
    }

    issue(0, 0);

    for (int ch = 0; ch < 16; ch++) {
        if (ch + 1 < 16) {
            issue(ch + 1, (ch + 1) & 1);
            asm volatile("cp.async.wait_group 1;");
        } else {
            asm volatile("cp.async.wait_group 0;");
        }
        __syncthreads();                      // chunk ch data visible
        const float* itb = it + (ch & 1) * ITB;

        #pragma unroll
        for (int kk = 0; kk < 8; kk++) {
            const float* tb = itb + kk*432 + c + 3;
            const float4* w4 = (const float4*)(wd + (ch*8 + kk)*12);
            float4 wa = w4[0], wb = w4[1];
            float  w8 = w4[2].x;
            float d0, d1, d2, d3;
            {   // rolling 6-row depthwise for 4 vertical pixels
                float a0 = tb[0],   a1 = tb[1],   a2 = tb[2];
                d0 = fmaf(a2, wa.z, fmaf(a1, wa.y, a0 * wa.x));
                a0 = tb[72];  a1 = tb[73];  a2 = tb[74];
                d0 = fmaf(a0, wa.w, d0); d0 = fmaf(a1, wb.x, d0); d0 = fmaf(a2, wb.y, d0);
                d1 = fmaf(a2, wa.z, fmaf(a1, wa.y, a0 * wa.x));
                a0 = tb[144]; a1 = tb[145]; a2 = tb[146];
                d0 = fmaf(a0, wb.z, d0); d0 = fmaf(a1, wb.w, d0); d0 = fmaf(a2, w8, d0);
                d1 = fmaf(a0, wa.w, d1); d1 = fmaf(a1, wb.x, d1); d1 = fmaf(a2, wb.y, d1);
                d2 = fmaf(a2, wa.z, fmaf(a1, wa.y, a0 * wa.x));
                a0 = tb[216]; a1 = tb[217]; a2 = tb[218];
                d1 = fmaf(a0, wb.z, d1); d1 = fmaf(a1, wb.w, d1); d1 = fmaf(a2, w8, d1);
                d2 = fmaf(a0, wa.w, d2); d2 = fmaf(a1, wb.x, d2); d2 = fmaf(a2, wb.y, d2);
                d3 = fmaf(a2, wa.z, fmaf(a1, wa.y, a0 * wa.x));
                a0 = tb[288]; a1 = tb[289]; a2 = tb[290];
                d2 = fmaf(a0, wb.z, d2); d2 = fmaf(a1, wb.w, d2); d2 = fmaf(a2, w8, d2);
                d3 = fmaf(a0, wa.w, d3); d3 = fmaf(a1, wb.x, d3); d3 = fmaf(a2, wb.y, d3);
                a0 = tb[360]; a1 = tb[361]; a2 = tb[362];
                d3 = fmaf(a0, wb.z, d3); d3 = fmaf(a1, wb.w, d3); d3 = fmaf(a2, w8, d3);
            }
            unsigned long long dd0 = pack2(d0, d0);
            unsigned long long dd1 = pack2(d1, d1);
            unsigned long long dd2 = pack2(d2, d2);
            unsigned long long dd3 = pack2(d3, d3);
            const ulonglong2* wr = (const ulonglong2*)(wph + (ch*8 + kk)*80 + og*20);
            #pragma unroll
            for (int q2 = 0; q2 < 5; q2++) {
                ulonglong2 w = wr[q2];
                ffma2(acc[     2*q2], dd0, w.x); ffma2(acc[     2*q2+1], dd0, w.y);
                ffma2(acc[10 + 2*q2], dd1, w.x); ffma2(acc[10 + 2*q2+1], dd1, w.y);
                ffma2(acc[20 + 2*q2], dd2, w.x); ffma2(acc[20 + 2*q2+1], dd2, w.y);
                ffma2(acc[30 + 2*q2], dd3, w.x); ffma2(acc[30 + 2*q2+1], dd3, w.y);
            }
        }
        __syncthreads();                      // buffer consumed -> reusable
    }

    // epilogue: coalesced scalar stores (lane = column)
    const int o0 = og * 20;
    #pragma unroll
    for (int p = 0; p < 4; p++) {
        const int y = gy0 + p, x = gx0 + c;
        float* ob = out + (size_t)b*82*HWW + y*WW + x;
        #pragma unroll
        for (int q = 0; q < 10; q++) {
            float2 f = unpack2(acc[p*10 + q]);
            ob[(size_t)(o0 + 2*q)   * HWW] = fmaxf(f.x, 0.f);
            ob[(size_t)(o0 + 2*q+1) * HWW] = fmaxf(f.y, 0.f);
        }
        if (og == 0) {   // flow passthrough ch 80/81
            ob[(size_t)80 * HWW] = flow[((size_t)b*2 + 0)*HWW + y*WW + x];
            ob[(size_t)81 * HWW] = flow[((size_t)b*2 + 1)*HWW + y*WW + x];
        }
    }
}

// ---------------- launch ----------------------------------------------------------
extern "C" void kernel_launch(void* const* d_in, const int* in_sizes, int n_in,
                              void* d_out, int out_size) {
    const float* flow = (const float*)d_in[0];
    const float* corr = (const float*)d_in[1];
    const float* Wc1  = (const float*)d_in[2];
    const float* bc1  = (const float*)d_in[3];
    const float* Wf1  = (const float*)d_in[4];
    const float* bf1  = (const float*)d_in[5];
    const float* Wf2  = (const float*)d_in[6];
    const float* bf2  = (const float*)d_in[7];
    const float* Wd   = (const float*)d_in[8];
    const float* Wp   = (const float*)d_in[9];
    const float* bp   = (const float*)d_in[10];
    float* out = (float*)d_out;

    const size_t cor_smem  = (size_t)(CP*96 + 96 + 2*KC*256) * sizeof(float);       // ~102 KB
    const size_t dwpw_smem = (size_t)(10240 + 1536 + 80 + 2*ITB) * sizeof(float);   // ~75 KB
    cudaFuncSetAttribute(corflo_kernel, cudaFuncAttributeMaxDynamicSharedMemorySize, (int)cor_smem);
    cudaFuncSetAttribute(dwpw_kernel,   cudaFuncAttributeMaxDynamicSharedMemorySize, (int)dwpw_smem);

    quant_init<<<1, 32>>>();
    quant_reduce<<<40, 256>>>(Wc1, Wf1, Wf2, Wd, Wp);
    quant_pack<<<40, 256>>>(Wc1, Wf1, Wf2, Wd, Wp);
    corflo_kernel<<<1536, 256, cor_smem>>>(corr, bc1, flow, bf1, bf2);
    dwpw_kernel<<<768, 256, dwpw_smem>>>(flow, bp, out);
}

// round 10
// speedup vs baseline: 2.9375x; 1.1372x over previous
#include <cuda_runtime.h>
#include <cstdint>

#define BB 16
#define HH 96
#define WW 128
#define HWW (HH*WW)          // 12288
#define NPIX (BB*HWW)        // 196608
#define CP 196
#define PH 98                // padded rows   (y+1)
#define PWS 136              // padded stride (x+4)
#define PPL (PH*PWS)         // 13328 floats / channel plane

// ---------------- packed-f32x2 helpers -----------------------------------------
__device__ __forceinline__ unsigned long long pack2(float x, float y) {
    unsigned long long r;
    asm("mov.b64 %0, {%1, %2};" : "=l"(r) : "f"(x), "f"(y));
    return r;
}
__device__ __forceinline__ void ffma2(unsigned long long& acc,
                                      unsigned long long a, unsigned long long b) {
    asm("fma.rn.f32x2 %0, %1, %2, %0;" : "+l"(acc) : "l"(a), "l"(b));
}
__device__ __forceinline__ float2 unpack2(unsigned long long v) {
    float2 f;
    asm("mov.b64 {%0, %1}, %2;" : "=f"(f.x), "=f"(f.y) : "l"(v));
    return f;
}
__device__ __forceinline__ void cp16(uint32_t dst, const void* src) {
    asm volatile("cp.async.cg.shared.global [%0], [%1], 16;" :: "r"(dst), "l"(src));
}

// ---------------- device scratch ------------------------------------------------
__device__ unsigned g_scmax[5];                   // maxabs bits per tensor
__device__ __align__(16) float g_Wc1q[CP*96];     // [k][96]
__device__ __align__(16) float g_Wf1q[64*2];
__device__ __align__(16) float g_Wf2q[64*32];     // [k][32]
__device__ __align__(16) float g_Wdq[128*12];     // [c][12] (9 taps + 3 zero pad)
__device__ __align__(16) float g_Wpq[128*80];     // [c][80]
// padded activations: zero-initialized BSS; borders NEVER written -> stay zero.
__device__ __align__(16) float g_cfp[(size_t)BB*128*PPL];

// ---------------- 1) quantization: init / reduce / pack ---------------------------
__device__ __forceinline__ void qmap(int bid, int& t, int& start, int& cnt) {
    if      (bid < 32)  { t = 0; start = bid * 588;        cnt = 588;  }
    else if (bid == 32) { t = 1; start = 0;                cnt = 128;  }
    else if (bid == 33) { t = 2; start = 0;                cnt = 2048; }
    else if (bid == 34) { t = 3; start = 0;                cnt = 1152; }
    else                { t = 4; start = (bid - 35) * 2048; cnt = 2048; }
}

__global__ void quant_init() { if (threadIdx.x < 5) g_scmax[threadIdx.x] = 0u; }

__global__ void quant_reduce(const float* __restrict__ Wc1,
                             const float* __restrict__ Wf1,
                             const float* __restrict__ Wf2,
                             const float* __restrict__ Wd,
                             const float* __restrict__ Wp) {
    __shared__ float red[256];
    int t, start, cnt;
    qmap(blockIdx.x, t, start, cnt);
    const float* src = (t==0) ? Wc1 : (t==1) ? Wf1 : (t==2) ? Wf2 : (t==3) ? Wd : Wp;

    float m = 0.f;
    for (int i = threadIdx.x; i < cnt; i += 256) m = fmaxf(m, fabsf(src[start + i]));
    red[threadIdx.x] = m;
    __syncthreads();
    for (int s = 128; s > 0; s >>= 1) {
        if (threadIdx.x < s) red[threadIdx.x] = fmaxf(red[threadIdx.x], red[threadIdx.x+s]);
        __syncthreads();
    }
    if (threadIdx.x == 0) atomicMax(&g_scmax[t], __float_as_uint(red[0]));
}

__global__ void quant_pack(const float* __restrict__ Wc1,
                           const float* __restrict__ Wf1,
                           const float* __restrict__ Wf2,
                           const float* __restrict__ Wd,
                           const float* __restrict__ Wp) {
    int t, start, cnt;
    qmap(blockIdx.x, t, start, cnt);
    const float* src = (t==0) ? Wc1 : (t==1) ? Wf1 : (t==2) ? Wf2 : (t==3) ? Wd : Wp;
    const float sc = fmaxf(__uint_as_float(g_scmax[t]), 1e-8f) / 127.f;

    for (int ii = threadIdx.x; ii < cnt; ii += 256) {
        int i = start + ii;
        float q = rintf(src[i] / sc);
        q = fminf(fmaxf(q, -127.f), 127.f) * sc;
        if      (t == 0) { int o = i / CP,  k = i % CP; g_Wc1q[k*96 + o] = q; }
        else if (t == 1) g_Wf1q[i] = q;
        else if (t == 2) { int o = i / 64,  k = i % 64; g_Wf2q[k*32 + o] = q; }
        else if (t == 3) { int c = i / 9,   j = i % 9;  g_Wdq[c*12 + j] = q; }
        else             { int o = i / 128, c = i % 128; g_Wpq[c*80 + o] = q; }
    }
}

// ---------------- 2) fused cor (48-ch halves) + flo -------------------------------
// blocks 0..1535 : cor. tile = blk>>1 (256 px), half = blk&1 (48 ch).
//                  Adjacent halves share the tile -> 2nd corr read hits L2.
// blocks 1536..  : flo, 256 pixels, thread = 1 px x 32 ch.
#define KC 14
#define NCHK 14
__global__ __launch_bounds__(256, 3) void corflo_kernel(const float* __restrict__ corr,
                                                        const float* __restrict__ bc1,
                                                        const float* __restrict__ flow,
                                                        const float* __restrict__ bf1,
                                                        const float* __restrict__ bf2) {
    extern __shared__ __align__(16) float sm[];
    const int tid = threadIdx.x;

    if (blockIdx.x >= 1536) {
        // ---------------- flo path ----------------
        float* w1 = sm;            // 128
        float* b1 = sm + 128;      // 64
        float* w2 = sm + 192;      // 2048 [k][32]
        float* b2 = sm + 2240;     // 32
        for (int i = tid; i < 128;  i += 256) w1[i] = g_Wf1q[i];
        for (int i = tid; i < 64;   i += 256) b1[i] = bf1[i];
        for (int i = tid; i < 2048; i += 256) w2[i] = g_Wf2q[i];
        for (int i = tid; i < 32;   i += 256) b2[i] = bf2[i];
        __syncthreads();

        int p  = (blockIdx.x - 1536) * 256 + tid;
        int b  = p / HWW, hw = p % HWW;
        float fx = flow[(size_t)b * 2 * HWW + hw];
        float fy = flow[(size_t)b * 2 * HWW + HWW + hw];

        unsigned long long acc[16];
        #pragma unroll
        for (int q = 0; q < 16; q++) acc[q] = pack2(b2[2*q], b2[2*q+1]);

        #pragma unroll 4
        for (int j = 0; j < 64; j++) {
            float h = fmaxf(fmaf(fx, w1[2*j], fmaf(fy, w1[2*j+1], b1[j])), 0.f);
            unsigned long long hh = pack2(h, h);
            const ulonglong2* wv = reinterpret_cast<const ulonglong2*>(w2 + j*32);
            #pragma unroll
            for (int q = 0; q < 8; q++) {
                ulonglong2 a = wv[q];
                ffma2(acc[2*q],   hh, a.x);
                ffma2(acc[2*q+1], hh, a.y);
            }
        }

        const int y = hw >> 7, x = hw & 127;
        float* obase = g_cfp + ((size_t)(b*128 + 96) * PH + (y+1)) * PWS + x + 4;
        #pragma unroll
        for (int q = 0; q < 16; q++) {
            float2 f = unpack2(acc[q]);
            obase[(size_t)(2*q)   * PPL] = fmaxf(f.x, 0.f);
            obase[(size_t)(2*q+1) * PPL] = fmaxf(f.y, 0.f);
        }
        return;
    }

    // ---------------- cor path: 48 of 96 channels ----------------
    float* Ws = sm;                    // [196][48] = 9408
    float* bs = Ws + CP*48;            // 48
    float* Xs = bs + 48;               // [2][14][256] = 7168

    const int half = blockIdx.x & 1;
    const int co   = half * 48;
    for (int i = tid; i < CP*48; i += 256) {
        int k = i / 48, j = i % 48;
        Ws[i] = g_Wc1q[k*96 + co + j];
    }
    if (tid < 48) bs[tid] = bc1[co + tid];

    const int tile = blockIdx.x >> 1;
    const int pix0 = tile * 256;
    const int b = pix0 / HWW, hw0 = pix0 % HWW;
    const float* cbase = corr + (size_t)b * CP * HWW + hw0;

    uint32_t xs_s = (uint32_t)__cvta_generic_to_shared(Xs);

    auto issue = [&](int c, int buf) {
        #pragma unroll
        for (int j = 0; j < 4; j++) {          // 14*64 = 896 float4
            int idx = tid + j*256;
            if (idx < 896) {
                int kk = idx >> 6, off = idx & 63;
                cp16(xs_s + (uint32_t)(((buf*KC + kk)*256 + off*4)*4),
                     cbase + (size_t)(c*KC + kk) * HWW + off*4);
            }
        }
        asm volatile("cp.async.commit_group;");
    };

    issue(0, 0);
    __syncthreads();   // Ws/bs visible

    const int po = tid >> 6, pg = tid & 63;    // 4 ch-groups of 12 x 64 pixel-quads

    unsigned long long acc[24];                // [p=4][jj=6] channel pairs
    #pragma unroll
    for (int jj = 0; jj < 6; jj++) {
        unsigned long long bv = pack2(bs[12*po + 2*jj], bs[12*po + 2*jj + 1]);
        acc[jj] = bv; acc[6+jj] = bv; acc[12+jj] = bv; acc[18+jj] = bv;
    }

    for (int c = 0; c < NCHK; c++) {
        if (c + 1 < NCHK) {
            issue(c + 1, (c + 1) & 1);
            asm volatile("cp.async.wait_group 1;");
        } else {
            asm volatile("cp.async.wait_group 0;");
        }
        __syncthreads();
        const float4* xsb = (const float4*)(Xs + (c & 1) * KC * 256);
        const float*  wrb = Ws + c * KC * 48 + 12 * po;
        #pragma unroll
        for (int kk = 0; kk < KC; kk++) {
            float4 xv = xsb[kk*64 + pg];
            unsigned long long x0 = pack2(xv.x, xv.x);
            unsigned long long x1 = pack2(xv.y, xv.y);
            unsigned long long x2 = pack2(xv.z, xv.z);
            unsigned long long x3 = pack2(xv.w, xv.w);
            const ulonglong2* wr = (const ulonglong2*)(wrb + kk*48);
            #pragma unroll
            for (int q2 = 0; q2 < 3; q2++) {
                ulonglong2 w = wr[q2];
                ffma2(acc[     2*q2], x0, w.x); ffma2(acc[     2*q2+1], x0, w.y);
                ffma2(acc[ 6 + 2*q2], x1, w.x); ffma2(acc[ 6 + 2*q2+1], x1, w.y);
                ffma2(acc[12 + 2*q2], x2, w.x); ffma2(acc[12 + 2*q2+1], x2, w.y);
                ffma2(acc[18 + 2*q2], x3, w.x); ffma2(acc[18 + 2*q2+1], x3, w.y);
            }
        }
        __syncthreads();   // buffer reuse fence
    }

    const int hw = hw0 + 4*pg;
    const int y = hw >> 7, x = hw & 127;
    float* ob = g_cfp + ((size_t)(b*128 + co + 12*po) * PH + (y+1)) * PWS + x + 4;
    #pragma unroll
    for (int jj = 0; jj < 6; jj++) {
        float2 f0 = unpack2(acc[jj]),    f1 = unpack2(acc[6+jj]);
        float2 f2 = unpack2(acc[12+jj]), f3 = unpack2(acc[18+jj]);
        float4 e = make_float4(fmaxf(f0.x,0.f), fmaxf(f1.x,0.f), fmaxf(f2.x,0.f), fmaxf(f3.x,0.f));
        float4 o = make_float4(fmaxf(f0.y,0.f), fmaxf(f1.y,0.f), fmaxf(f2.y,0.f), fmaxf(f3.y,0.f));
        *(float4*)(ob + (size_t)(2*jj)   * PPL) = e;
        *(float4*)(ob + (size_t)(2*jj+1) * PPL) = o;
    }
}

// ---------------- 3) fused dw3x3 + pw 128->80 : phase A/B -------------------------
// grid 768: pixel tile 64w x 4h; 256 threads. Chunks of 8 channels.
// Phase A: 8 thr-groups of 32 compute dw once per channel into dwb[8][260].
// Phase B: GEMM, thread = 4 horizontal px (float4) x 20 outputs.
#define ITB 3456    // floats per halo buffer: 8 ch * 6 rows * 72
#define DWS 260     // dwb channel stride (floats, 16B-aligned)
__global__ __launch_bounds__(256, 2) void dwpw_kernel(const float* __restrict__ flow,
                                                      const float* __restrict__ bp,
                                                      float* __restrict__ out) {
    extern __shared__ __align__(16) float sm2[];
    float* wph = sm2;              // [128][80]  = 10240
    float* wd  = wph + 10240;      // [128][12]  = 1536
    float* bph = wd + 1536;        // 80
    float* it  = bph + 80;         // 2 x [8][6][72] = 6912
    float* dwb = it + 2*ITB;       // [8][260]   = 2080

    const int tid = threadIdx.x;
    for (int i = tid; i < 10240/4; i += 256) ((float4*)wph)[i] = ((const float4*)g_Wpq)[i];
    for (int i = tid; i < 1536/4;  i += 256) ((float4*)wd)[i]  = ((const float4*)g_Wdq)[i];
    if (tid < 80) bph[tid] = bp[tid];

    const int blk = blockIdx.x;              // 768 tiles: 16b x 24y x 2x
    const int b = blk / 48, t = blk % 48;
    const int gy0 = (t >> 1) * 4, gx0 = (t & 1) * 64;
    const int cl = tid >> 5, l  = tid & 31;  // phase A: channel-in-chunk, lane
    const int og = tid >> 6, pg = tid & 63;  // phase B: ch-group, pixel-quad

    const float* cfb = g_cfp + (size_t)b * 128 * PPL;
    uint32_t it_s = (uint32_t)__cvta_generic_to_shared(it);

    auto issue = [&](int ch, int buf) {      // 8 ch x 6 rows x 18 float4 = 864
        const float* srcbase = cfb + (size_t)(ch*8) * PPL + gy0 * PWS + gx0;
        #pragma unroll
        for (int j = 0; j < 4; j++) {
            int idx = tid + j*256;
            if (idx < 864) {
                int c8 = idx / 108, rem = idx % 108;
                int ry = rem / 18,  rx  = rem % 18;
                cp16(it_s + (uint32_t)((buf*ITB + c8*432 + ry*72 + rx*4)*4),
                     srcbase + (size_t)c8*PPL + ry*PWS + rx*4);
            }
        }
        asm volatile("cp.async.commit_group;");
    };

    __syncthreads();                          // weights visible

    unsigned long long acc[40];               // [p=4][q=10] channel pairs
    #pragma unroll
    for (int q = 0; q < 10; q++) {
        unsigned long long bv = pack2(bph[og*20 + 2*q], bph[og*20 + 2*q + 1]);
        acc[q] = bv; acc[10+q] = bv; acc[20+q] = bv; acc[30+q] = bv;
    }

    issue(0, 0);

    for (int ch = 0; ch < 16; ch++) {
        if (ch + 1 < 16) {
            issue(ch + 1, (ch + 1) & 1);
            asm volatile("cp.async.wait_group 1;");
        } else {
            asm volatile("cp.async.wait_group 0;");
        }
        __syncthreads();                      // halo ready; dwb free (prev B done)
        const float* itb = it + (ch & 1) * ITB;

        // ---- phase A: depthwise once per channel ----
        {
            const float4* w4 = (const float4*)(wd + (ch*8 + cl)*12);
            float4 wa = w4[0], wb = w4[1];
            float  w8 = w4[2].x;
            #pragma unroll
            for (int hx = 0; hx < 2; hx++) {
                const int x = l + 32*hx;
                const float* tb = itb + cl*432 + x + 3;
                float d0, d1, d2, d3;
                {   // rolling 6-row dw for 4 vertical pixels
                    float a0 = tb[0],   a1 = tb[1],   a2 = tb[2];
                    d0 = fmaf(a2, wa.z, fmaf(a1, wa.y, a0 * wa.x));
                    a0 = tb[72];  a1 = tb[73];  a2 = tb[74];
                    d0 = fmaf(a0, wa.w, d0); d0 = fmaf(a1, wb.x, d0); d0 = fmaf(a2, wb.y, d0);
                    d1 = fmaf(a2, wa.z, fmaf(a1, wa.y, a0 * wa.x));
                    a0 = tb[144]; a1 = tb[145]; a2 = tb[146];
                    d0 = fmaf(a0, wb.z, d0); d0 = fmaf(a1, wb.w, d0); d0 = fmaf(a2, w8, d0);
                    d1 = fmaf(a0, wa.w, d1); d1 = fmaf(a1, wb.x, d1); d1 = fmaf(a2, wb.y, d1);
                    d2 = fmaf(a2, wa.z, fmaf(a1, wa.y, a0 * wa.x));
                    a0 = tb[216]; a1 = tb[217]; a2 = tb[218];
                    d1 = fmaf(a0, wb.z, d1); d1 = fmaf(a1, wb.w, d1); d1 = fmaf(a2, w8, d1);
                    d2 = fmaf(a0, wa.w, d2); d2 = fmaf(a1, wb.x, d2); d2 = fmaf(a2, wb.y, d2);
                    d3 = fmaf(a2, wa.z, fmaf(a1, wa.y, a0 * wa.x));
                    a0 = tb[288]; a1 = tb[289]; a2 = tb[290];
                    d2 = fmaf(a0, wb.z, d2); d2 = fmaf(a1, wb.w, d2); d2 = fmaf(a2, w8, d2);
                    d3 = fmaf(a0, wa.w, d3); d3 = fmaf(a1, wb.x, d3); d3 = fmaf(a2, wb.y, d3);
                    a0 = tb[360]; a1 = tb[361]; a2 = tb[362];
                    d3 = fmaf(a0, wb.z, d3); d3 = fmaf(a1, wb.w, d3); d3 = fmaf(a2, w8, d3);
                }
                float* dst = dwb + cl*DWS + x;
                dst[0] = d0; dst[64] = d1; dst[128] = d2; dst[192] = d3;
            }
        }
        __syncthreads();                      // dwb visible

        // ---- phase B: 8-k GEMM ----
        #pragma unroll
        for (int kk = 0; kk < 8; kk++) {
            float4 xv = *(const float4*)(dwb + kk*DWS + 4*pg);
            unsigned long long dd0 = pack2(xv.x, xv.x);
            unsigned long long dd1 = pack2(xv.y, xv.y);
            unsigned long long dd2 = pack2(xv.z, xv.z);
            unsigned long long dd3 = pack2(xv.w, xv.w);
            const ulonglong2* wr = (const ulonglong2*)(wph + (ch*8 + kk)*80 + og*20);
            #pragma unroll
            for (int q2 = 0; q2 < 5; q2++) {
                ulonglong2 w = wr[q2];
                ffma2(acc[     2*q2], dd0, w.x); ffma2(acc[     2*q2+1], dd0, w.y);
                ffma2(acc[10 + 2*q2], dd1, w.x); ffma2(acc[10 + 2*q2+1], dd1, w.y);
                ffma2(acc[20 + 2*q2], dd2, w.x); ffma2(acc[20 + 2*q2+1], dd2, w.y);
                ffma2(acc[30 + 2*q2], dd3, w.x); ffma2(acc[30 + 2*q2+1], dd3, w.y);
            }
        }
    }

    // epilogue: float4 stores, thread = 4 horizontal px (px 4*pg..4*pg+3)
    const int o0 = og * 20;
    const int y = gy0 + (pg >> 4), x0 = gx0 + ((4*pg) & 63);
    float* ob = out + (size_t)b*82*HWW + y*WW + x0;
    #pragma unroll
    for (int q = 0; q < 10; q++) {
        float2 f0 = unpack2(acc[q]),    f1 = unpack2(acc[10+q]);
        float2 f2 = unpack2(acc[20+q]), f3 = unpack2(acc[30+q]);
        float4 e = make_float4(fmaxf(f0.x,0.f), fmaxf(f1.x,0.f), fmaxf(f2.x,0.f), fmaxf(f3.x,0.f));
        float4 o = make_float4(fmaxf(f0.y,0.f), fmaxf(f1.y,0.f), fmaxf(f2.y,0.f), fmaxf(f3.y,0.f));
        *(float4*)(ob + (size_t)(o0 + 2*q)   * HWW) = e;
        *(float4*)(ob + (size_t)(o0 + 2*q+1) * HWW) = o;
    }
    if (og == 0) {   // flow passthrough ch 80/81
        float4 f0 = *(const float4*)(flow + ((size_t)b*2 + 0)*HWW + y*WW + x0);
        float4 f1 = *(const float4*)(flow + ((size_t)b*2 + 1)*HWW + y*WW + x0);
        *(float4*)(out + ((size_t)b*82 + 80)*HWW + y*WW + x0) = f0;
        *(float4*)(out + ((size_t)b*82 + 81)*HWW + y*WW + x0) = f1;
    }
}

// ---------------- launch ----------------------------------------------------------
extern "C" void kernel_launch(void* const* d_in, const int* in_sizes, int n_in,
                              void* d_out, int out_size) {
    const float* flow = (const float*)d_in[0];
    const float* corr = (const float*)d_in[1];
    const float* Wc1  = (const float*)d_in[2];
    const float* bc1  = (const float*)d_in[3];
    const float* Wf1  = (const float*)d_in[4];
    const float* bf1  = (const float*)d_in[5];
    const float* Wf2  = (const float*)d_in[6];
    const float* bf2  = (const float*)d_in[7];
    const float* Wd   = (const float*)d_in[8];
    const float* Wp   = (const float*)d_in[9];
    const float* bp   = (const float*)d_in[10];
    float* out = (float*)d_out;

    const size_t cor_smem  = (size_t)(CP*48 + 48 + 2*KC*256) * sizeof(float);            // ~65 KB
    const size_t dwpw_smem = (size_t)(10240 + 1536 + 80 + 2*ITB + 8*DWS) * sizeof(float); // ~82 KB
    cudaFuncSetAttribute(corflo_kernel, cudaFuncAttributeMaxDynamicSharedMemorySize, (int)cor_smem);
    cudaFuncSetAttribute(dwpw_kernel,   cudaFuncAttributeMaxDynamicSharedMemorySize, (int)dwpw_smem);

    quant_init<<<1, 32>>>();
    quant_reduce<<<40, 256>>>(Wc1, Wf1, Wf2, Wd, Wp);
    quant_pack<<<40, 256>>>(Wc1, Wf1, Wf2, Wd, Wp);
    corflo_kernel<<<1536 + 768, 256, cor_smem>>>(corr, bc1, flow, bf1, bf2);
    dwpw_kernel<<<768, 256, dwpw_smem>>>(flow, bp, out);
}